// round 5
// baseline (speedup 1.0000x reference)
#include <cuda_runtime.h>

// Problem constants (fixed by the dataset)
#define NN   10000
#define EE   320000
#define HH   4
#define CIN  256
#define FF   512          // H*HID = H*OUT = per-node feature width in both layers
#define COUT 128
#define SLOPE 0.2f

// ---------------- scratch (static device globals; no allocation) ----------------
__device__ float g_h1[NN * FF];
__device__ float g_agg1[NN * FF];
__device__ float g_h2[NN * FF];
__device__ float g_as1[NN * HH];
__device__ float g_ad1[NN * HH];
__device__ float g_as2[NN * HH];
__device__ float g_ad2[NN * HH];
__device__ int   g_counts[NN];
__device__ int   g_rowptr[NN + 1];
__device__ int   g_cursor[NN];
__device__ int   g_srcsorted[EE + NN];

// ---------------- CSR build ----------------
__global__ void k_initcount(int n) {
    int i = blockIdx.x * blockDim.x + threadIdx.x;
    if (i < n) g_counts[i] = 1;   // self loop
}

__global__ void k_count(const int* __restrict__ ei, int E) {
    int i = blockIdx.x * blockDim.x + threadIdx.x;
    if (i < E) atomicAdd(&g_counts[ei[E + i]], 1);
}

// single-block exclusive scan of g_counts -> g_rowptr, g_cursor
__global__ void k_scan(int n) {
    __shared__ int sb[1024];
    int tid = threadIdx.x;
    int per = (n + 1023) >> 10;
    int base = tid * per;
    int sum = 0;
    for (int i = 0; i < per; i++) {
        int idx = base + i;
        if (idx < n) sum += g_counts[idx];
    }
    sb[tid] = sum;
    __syncthreads();
    for (int off = 1; off < 1024; off <<= 1) {
        int v = (tid >= off) ? sb[tid - off] : 0;
        __syncthreads();
        sb[tid] += v;
        __syncthreads();
    }
    int run = sb[tid] - sum;   // exclusive prefix
    for (int i = 0; i < per; i++) {
        int idx = base + i;
        if (idx < n) {
            g_rowptr[idx] = run;
            g_cursor[idx] = run;
            run += g_counts[idx];
        }
    }
    if (tid == 1023) g_rowptr[n] = sb[1023];
}

__global__ void k_scatter(const int* __restrict__ ei, int E, int n) {
    int i = blockIdx.x * blockDim.x + threadIdx.x;
    int total = E + n;
    if (i >= total) return;
    int s, d;
    if (i < E) { s = ei[i]; d = ei[E + i]; }
    else       { s = i - E; d = s; }
    int pos = atomicAdd(&g_cursor[d], 1);
    g_srcsorted[pos] = s;
}

// ---------------- SGEMM: C[M,N] = op(A)[M,K] @ B[K,N], fp32 ----------------
// 128x128 block tile, BK=8, 256 threads, 8x8 per-thread micro-tile.
template <bool RELU_A>
__global__ __launch_bounds__(256)
void k_sgemm(const float* __restrict__ A, const float* __restrict__ B,
             float* __restrict__ C, int M, int N, int K)
{
    __shared__ float As[8][128];
    __shared__ float Bs[8][128];

    const int tid  = threadIdx.x;
    const int brow = blockIdx.y * 128;
    const int bcol = blockIdx.x * 128;

    const int aRow = tid >> 1;          // 0..127
    const int aCol = (tid & 1) * 4;     // 0 or 4
    const int bRow = tid >> 5;          // 0..7
    const int bCol = (tid & 31) * 4;    // 0..124

    const int ty = tid >> 4;            // 0..15
    const int tx = tid & 15;            // 0..15

    float acc[8][8];
#pragma unroll
    for (int i = 0; i < 8; i++)
#pragma unroll
        for (int j = 0; j < 8; j++) acc[i][j] = 0.f;

    for (int k0 = 0; k0 < K; k0 += 8) {
        // load A tile (guard M), optionally relu
        float4 av = make_float4(0.f, 0.f, 0.f, 0.f);
        int gr = brow + aRow;
        if (gr < M)
            av = *reinterpret_cast<const float4*>(A + (size_t)gr * K + k0 + aCol);
        if (RELU_A) {
            av.x = fmaxf(av.x, 0.f); av.y = fmaxf(av.y, 0.f);
            av.z = fmaxf(av.z, 0.f); av.w = fmaxf(av.w, 0.f);
        }
        As[aCol + 0][aRow] = av.x;
        As[aCol + 1][aRow] = av.y;
        As[aCol + 2][aRow] = av.z;
        As[aCol + 3][aRow] = av.w;

        // load B tile (N,K are multiples of tile sizes)
        float4 bv = *reinterpret_cast<const float4*>(B + (size_t)(k0 + bRow) * N + bcol + bCol);
        *reinterpret_cast<float4*>(&Bs[bRow][bCol]) = bv;

        __syncthreads();

#pragma unroll
        for (int kk = 0; kk < 8; kk++) {
            float a[8], b[8];
            *reinterpret_cast<float4*>(a)     = *reinterpret_cast<const float4*>(&As[kk][ty * 8]);
            *reinterpret_cast<float4*>(a + 4) = *reinterpret_cast<const float4*>(&As[kk][ty * 8 + 4]);
            *reinterpret_cast<float4*>(b)     = *reinterpret_cast<const float4*>(&Bs[kk][tx * 8]);
            *reinterpret_cast<float4*>(b + 4) = *reinterpret_cast<const float4*>(&Bs[kk][tx * 8 + 4]);
#pragma unroll
            for (int i = 0; i < 8; i++)
#pragma unroll
                for (int j = 0; j < 8; j++)
                    acc[i][j] = fmaf(a[i], b[j], acc[i][j]);
        }
        __syncthreads();
    }

#pragma unroll
    for (int i = 0; i < 8; i++) {
        int r = brow + ty * 8 + i;
        if (r < M) {
            float* cp = C + (size_t)r * N + bcol + tx * 8;
            *reinterpret_cast<float4*>(cp)     = make_float4(acc[i][0], acc[i][1], acc[i][2], acc[i][3]);
            *reinterpret_cast<float4*>(cp + 4) = make_float4(acc[i][4], acc[i][5], acc[i][6], acc[i][7]);
        }
    }
}

// ---------------- attention coefficients: as[n,h] = <h[n,h,:], a_src[h,:]> ----------------
__global__ void k_attn(const float* __restrict__ hfeat,
                       const float* __restrict__ a_src, const float* __restrict__ a_dst,
                       float* __restrict__ as, float* __restrict__ ad, int n)
{
    int w = (blockIdx.x * blockDim.x + threadIdx.x) >> 5;
    int lane = threadIdx.x & 31;
    if (w >= n) return;
    const float* hp = hfeat + (size_t)w * FF;
#pragma unroll
    for (int h = 0; h < HH; h++) {
        float ps = 0.f, pd = 0.f;
#pragma unroll
        for (int c = 0; c < 128; c += 32) {
            float hv = hp[h * 128 + c + lane];
            ps = fmaf(hv, a_src[h * 128 + c + lane], ps);
            pd = fmaf(hv, a_dst[h * 128 + c + lane], pd);
        }
#pragma unroll
        for (int off = 16; off; off >>= 1) {
            ps += __shfl_xor_sync(0xffffffffu, ps, off);
            pd += __shfl_xor_sync(0xffffffffu, pd, off);
        }
        if (lane == 0) { as[w * HH + h] = ps; ad[w * HH + h] = pd; }
    }
}

__device__ __forceinline__ float lrelu(float z) { return z > 0.f ? z : SLOPE * z; }
__device__ __forceinline__ float sel4(float4 a, int h) {
    float v = a.x;
    if (h == 1) v = a.y;
    if (h == 2) v = a.z;
    if (h == 3) v = a.w;
    return v;
}

// ---------------- per-dst aggregation with segment softmax ----------------
// one warp per dst node; 3 passes: max, denom, weighted feature sum.
template <bool MEAN>
__global__ __launch_bounds__(256)
void k_agg(const float* __restrict__ hfeat, const float* __restrict__ as,
           const float* __restrict__ ad, const float* __restrict__ bias,
           float* __restrict__ out, int n)
{
    int w = (blockIdx.x * blockDim.x + threadIdx.x) >> 5;
    if (w >= n) return;
    int lane = threadIdx.x & 31;
    int start = g_rowptr[w], end = g_rowptr[w + 1];

    float4 adv = *reinterpret_cast<const float4*>(ad + (size_t)w * 4);

    // pass 1: per-head max
    float m0 = -3.4e38f, m1 = -3.4e38f, m2 = -3.4e38f, m3 = -3.4e38f;
    for (int j = start + lane; j < end; j += 32) {
        int s = g_srcsorted[j];
        float4 a = *reinterpret_cast<const float4*>(as + (size_t)s * 4);
        m0 = fmaxf(m0, lrelu(a.x + adv.x));
        m1 = fmaxf(m1, lrelu(a.y + adv.y));
        m2 = fmaxf(m2, lrelu(a.z + adv.z));
        m3 = fmaxf(m3, lrelu(a.w + adv.w));
    }
#pragma unroll
    for (int off = 16; off; off >>= 1) {
        m0 = fmaxf(m0, __shfl_xor_sync(0xffffffffu, m0, off));
        m1 = fmaxf(m1, __shfl_xor_sync(0xffffffffu, m1, off));
        m2 = fmaxf(m2, __shfl_xor_sync(0xffffffffu, m2, off));
        m3 = fmaxf(m3, __shfl_xor_sync(0xffffffffu, m3, off));
    }

    // pass 2: per-head sum of exp
    float d0 = 0.f, d1 = 0.f, d2 = 0.f, d3 = 0.f;
    for (int j = start + lane; j < end; j += 32) {
        int s = g_srcsorted[j];
        float4 a = *reinterpret_cast<const float4*>(as + (size_t)s * 4);
        d0 += __expf(lrelu(a.x + adv.x) - m0);
        d1 += __expf(lrelu(a.y + adv.y) - m1);
        d2 += __expf(lrelu(a.z + adv.z) - m2);
        d3 += __expf(lrelu(a.w + adv.w) - m3);
    }
#pragma unroll
    for (int off = 16; off; off >>= 1) {
        d0 += __shfl_xor_sync(0xffffffffu, d0, off);
        d1 += __shfl_xor_sync(0xffffffffu, d1, off);
        d2 += __shfl_xor_sync(0xffffffffu, d2, off);
        d3 += __shfl_xor_sync(0xffffffffu, d3, off);
    }
    float i0 = 1.f / (d0 + 1e-16f);
    float i1 = 1.f / (d1 + 1e-16f);
    float i2 = 1.f / (d2 + 1e-16f);
    float i3 = 1.f / (d3 + 1e-16f);

    // pass 3: weighted sum of features. Lane owns 16 contiguous channels
    // c_full = lane*16 + {0..15}; head = lane>>3 (16 | 128 so a lane never straddles heads).
    const int hsel = lane >> 3;
    const float mm = sel4(make_float4(m0, m1, m2, m3), hsel);
    const float ii = sel4(make_float4(i0, i1, i2, i3), hsel);
    const float aD = sel4(adv, hsel);

    float4 acc[4];
#pragma unroll
    for (int k = 0; k < 4; k++) acc[k] = make_float4(0.f, 0.f, 0.f, 0.f);

    for (int j = start; j < end; j++) {
        int s = g_srcsorted[j];
        float4 a = *reinterpret_cast<const float4*>(as + (size_t)s * 4);
        float wgt = __expf(lrelu(sel4(a, hsel) + aD) - mm) * ii;
        const float4* hp4 = reinterpret_cast<const float4*>(hfeat + (size_t)s * FF) + lane * 4;
#pragma unroll
        for (int k = 0; k < 4; k++) {
            float4 v = hp4[k];
            acc[k].x = fmaf(wgt, v.x, acc[k].x);
            acc[k].y = fmaf(wgt, v.y, acc[k].y);
            acc[k].z = fmaf(wgt, v.z, acc[k].z);
            acc[k].w = fmaf(wgt, v.w, acc[k].w);
        }
    }

    if (!MEAN) {
        float4* op = reinterpret_cast<float4*>(out + (size_t)w * FF);
        const float4* bp = reinterpret_cast<const float4*>(bias);
#pragma unroll
        for (int k = 0; k < 4; k++) {
            float4 b4 = bp[lane * 4 + k];
            float4 v = acc[k];
            v.x += b4.x; v.y += b4.y; v.z += b4.z; v.w += b4.w;
            op[lane * 4 + k] = v;
        }
    } else {
        // mean over heads: sum lanes {l, l^8, l^16, l^24}, lanes 0..7 write 128 channels
#pragma unroll
        for (int k = 0; k < 4; k++) {
            acc[k].x += __shfl_xor_sync(0xffffffffu, acc[k].x, 8);
            acc[k].y += __shfl_xor_sync(0xffffffffu, acc[k].y, 8);
            acc[k].z += __shfl_xor_sync(0xffffffffu, acc[k].z, 8);
            acc[k].w += __shfl_xor_sync(0xffffffffu, acc[k].w, 8);
            acc[k].x += __shfl_xor_sync(0xffffffffu, acc[k].x, 16);
            acc[k].y += __shfl_xor_sync(0xffffffffu, acc[k].y, 16);
            acc[k].z += __shfl_xor_sync(0xffffffffu, acc[k].z, 16);
            acc[k].w += __shfl_xor_sync(0xffffffffu, acc[k].w, 16);
        }
        if (lane < 8) {
            float4* op = reinterpret_cast<float4*>(out + (size_t)w * COUT);
            const float4* bp = reinterpret_cast<const float4*>(bias);
#pragma unroll
            for (int k = 0; k < 4; k++) {
                float4 b4 = bp[lane * 4 + k];
                float4 v = acc[k];
                v.x = 0.25f * v.x + b4.x; v.y = 0.25f * v.y + b4.y;
                v.z = 0.25f * v.z + b4.z; v.w = 0.25f * v.w + b4.w;
                op[lane * 4 + k] = v;
            }
        }
    }
}

// ---------------- host ----------------
extern "C" void kernel_launch(void* const* d_in, const int* in_sizes, int n_in,
                              void* d_out, int out_size)
{
    const float* x      = (const float*)d_in[0];
    const int*   ei     = (const int*)d_in[1];
    const float* W1     = (const float*)d_in[2];
    const float* a_src1 = (const float*)d_in[3];
    const float* a_dst1 = (const float*)d_in[4];
    const float* b1     = (const float*)d_in[5];
    const float* W2     = (const float*)d_in[6];
    const float* a_src2 = (const float*)d_in[7];
    const float* a_dst2 = (const float*)d_in[8];
    const float* b2     = (const float*)d_in[9];

    const int N = in_sizes[0] / CIN;
    const int E = in_sizes[1] / 2;

    void *p_h1, *p_agg1, *p_h2, *p_as1, *p_ad1, *p_as2, *p_ad2;
    cudaGetSymbolAddress(&p_h1,  g_h1);
    cudaGetSymbolAddress(&p_agg1, g_agg1);
    cudaGetSymbolAddress(&p_h2,  g_h2);
    cudaGetSymbolAddress(&p_as1, g_as1);
    cudaGetSymbolAddress(&p_ad1, g_ad1);
    cudaGetSymbolAddress(&p_as2, g_as2);
    cudaGetSymbolAddress(&p_ad2, g_ad2);
    float* h1   = (float*)p_h1;
    float* agg1 = (float*)p_agg1;
    float* h2   = (float*)p_h2;
    float* as1  = (float*)p_as1;
    float* ad1  = (float*)p_ad1;
    float* as2  = (float*)p_as2;
    float* ad2  = (float*)p_ad2;
    float* out  = (float*)d_out;

    // CSR build (deterministic work every call)
    k_initcount<<<(N + 255) / 256, 256>>>(N);
    k_count<<<(E + 255) / 256, 256>>>(ei, E);
    k_scan<<<1, 1024>>>(N);
    k_scatter<<<(E + N + 255) / 256, 256>>>(ei, E, N);

    const int warpsGrid = (N * 32 + 255) / 256;

    // layer 1
    dim3 g1(FF / 128, (N + 127) / 128);
    k_sgemm<false><<<g1, 256>>>(x, W1, h1, N, FF, CIN);
    k_attn<<<warpsGrid, 256>>>(h1, a_src1, a_dst1, as1, ad1, N);
    k_agg<false><<<warpsGrid, 256>>>(h1, as1, ad1, b1, agg1, N);

    // layer 2 (ReLU fused into GEMM2's A-load)
    dim3 g2(FF / 128, (N + 127) / 128);
    k_sgemm<true><<<g2, 256>>>(agg1, W2, h2, N, FF, FF);
    k_attn<<<warpsGrid, 256>>>(h2, a_src2, a_dst2, as2, ad2, N);
    k_agg<true><<<warpsGrid, 256>>>(h2, as2, ad2, b2, out, N);
}

// round 7
// speedup vs baseline: 1.0695x; 1.0695x over previous
#include <cuda_runtime.h>
#include <cstdint>

// Problem constants (fixed by the dataset)
#define NN   10000
#define EE   320000
#define HH   4
#define CIN  256
#define FF   512          // H*HID = H*OUT = per-node feature width in both layers
#define COUT 128
#define SLOPE 0.2f

// ---------------- scratch (static device globals; no allocation) ----------------
__device__ float g_h1[NN * FF];
__device__ float g_agg1[NN * FF];
__device__ float g_h2[NN * FF];
__device__ float g_as1[NN * HH];
__device__ float g_ad1[NN * HH];
__device__ float g_as2[NN * HH];
__device__ float g_ad2[NN * HH];
__device__ int   g_counts[NN];
__device__ int   g_rowptr[NN + 1];
__device__ int   g_cursor[NN];
__device__ int   g_srcsorted[EE + NN];

// ---------------- CSR build ----------------
__global__ void k_initcount(int n) {
    int i = blockIdx.x * blockDim.x + threadIdx.x;
    if (i < n) g_counts[i] = 1;   // self loop
}

__global__ void k_count(const int* __restrict__ ei, int E) {
    int i = blockIdx.x * blockDim.x + threadIdx.x;
    if (i < E) atomicAdd(&g_counts[ei[E + i]], 1);
}

// single-block exclusive scan of g_counts -> g_rowptr, g_cursor
__global__ void k_scan(int n) {
    __shared__ int sb[1024];
    int tid = threadIdx.x;
    int per = (n + 1023) >> 10;
    int base = tid * per;
    int sum = 0;
    for (int i = 0; i < per; i++) {
        int idx = base + i;
        if (idx < n) sum += g_counts[idx];
    }
    sb[tid] = sum;
    __syncthreads();
    for (int off = 1; off < 1024; off <<= 1) {
        int v = (tid >= off) ? sb[tid - off] : 0;
        __syncthreads();
        sb[tid] += v;
        __syncthreads();
    }
    int run = sb[tid] - sum;   // exclusive prefix
    for (int i = 0; i < per; i++) {
        int idx = base + i;
        if (idx < n) {
            g_rowptr[idx] = run;
            g_cursor[idx] = run;
            run += g_counts[idx];
        }
    }
    if (tid == 1023) g_rowptr[n] = sb[1023];
}

__global__ void k_scatter(const int* __restrict__ ei, int E, int n) {
    int i = blockIdx.x * blockDim.x + threadIdx.x;
    int total = E + n;
    if (i >= total) return;
    int s, d;
    if (i < E) { s = ei[i]; d = ei[E + i]; }
    else       { s = i - E; d = s; }
    int pos = atomicAdd(&g_cursor[d], 1);
    g_srcsorted[pos] = s;
}

// ---------------- packed f32x2 helpers ----------------
__device__ __forceinline__ unsigned long long dup_f32x2(float v) {
    unsigned long long r;
    uint32_t b = __float_as_uint(v);
    asm("mov.b64 %0, {%1, %1};" : "=l"(r) : "r"(b));
    return r;
}
__device__ __forceinline__ void ffma2(unsigned long long& acc,
                                      unsigned long long a, unsigned long long b) {
    asm("fma.rn.f32x2 %0, %1, %2, %0;" : "+l"(acc) : "l"(a), "l"(b));
}
__device__ __forceinline__ float2 unpack_f32x2(unsigned long long v) {
    uint32_t lo, hi;
    asm("mov.b64 {%0, %1}, %2;" : "=r"(lo), "=r"(hi) : "l"(v));
    return make_float2(__uint_as_float(lo), __uint_as_float(hi));
}

// ---------------- SGEMM: C[M,N] = op(A)[M,K] @ B[K,N], fp32, FFMA2 ----------------
// 128x128 block tile, BK=8, 256 threads, 8x8 per-thread micro-tile held as
// 8x4 packed f32x2 accumulators. SMEM double-buffered: one barrier per K-step.
template <bool RELU_A>
__global__ __launch_bounds__(256)
void k_sgemm(const float* __restrict__ A, const float* __restrict__ B,
             float* __restrict__ C, int M, int N, int K)
{
    __shared__ float As[2][8][128];
    __shared__ float Bs[2][8][128];

    const int tid  = threadIdx.x;
    const int brow = blockIdx.y * 128;
    const int bcol = blockIdx.x * 128;

    const int aRow = tid >> 1;          // 0..127
    const int aCol = (tid & 1) * 4;     // 0 or 4
    const int bRow = tid >> 5;          // 0..7
    const int bCol = (tid & 31) * 4;    // 0..124

    const int ty = tid >> 4;            // 0..15
    const int tx = tid & 15;            // 0..15

    const int gr = brow + aRow;
    const bool okA = gr < M;
    const float* Abase = A + (size_t)gr * K + aCol;
    const float* Bbase = B + (size_t)bRow * N + bcol + bCol;

    unsigned long long acc2[8][4];
#pragma unroll
    for (int i = 0; i < 8; i++)
#pragma unroll
        for (int j = 0; j < 4; j++) acc2[i][j] = 0ull;

    // preload first tile
    float4 av = make_float4(0.f, 0.f, 0.f, 0.f);
    if (okA) av = *reinterpret_cast<const float4*>(Abase);
    float4 bv = *reinterpret_cast<const float4*>(Bbase);

    const int nk = K >> 3;
    for (int t = 0; t < nk; t++) {
        const int cur = t & 1;
        // store staged tile into buffer 'cur'
        {
            float4 a = av;
            if (RELU_A) {
                a.x = fmaxf(a.x, 0.f); a.y = fmaxf(a.y, 0.f);
                a.z = fmaxf(a.z, 0.f); a.w = fmaxf(a.w, 0.f);
            }
            As[cur][aCol + 0][aRow] = a.x;
            As[cur][aCol + 1][aRow] = a.y;
            As[cur][aCol + 2][aRow] = a.z;
            As[cur][aCol + 3][aRow] = a.w;
            *reinterpret_cast<float4*>(&Bs[cur][bRow][bCol]) = bv;
        }
        __syncthreads();

        // prefetch next tile (global -> regs), overlapped with compute below
        if (t + 1 < nk) {
            if (okA) av = *reinterpret_cast<const float4*>(Abase + (t + 1) * 8);
            bv = *reinterpret_cast<const float4*>(Bbase + (size_t)(t + 1) * 8 * N);
        }

#pragma unroll
        for (int kk = 0; kk < 8; kk++) {
            float a[8];
            *reinterpret_cast<float4*>(a)     = *reinterpret_cast<const float4*>(&As[cur][kk][ty * 8]);
            *reinterpret_cast<float4*>(a + 4) = *reinterpret_cast<const float4*>(&As[cur][kk][ty * 8 + 4]);
            unsigned long long b2[4];
            {
                const ulonglong2* bp = reinterpret_cast<const ulonglong2*>(&Bs[cur][kk][tx * 8]);
                ulonglong2 q0 = bp[0], q1 = bp[1];
                b2[0] = q0.x; b2[1] = q0.y; b2[2] = q1.x; b2[3] = q1.y;
            }
#pragma unroll
            for (int i = 0; i < 8; i++) {
                unsigned long long ad = dup_f32x2(a[i]);
#pragma unroll
                for (int j = 0; j < 4; j++)
                    ffma2(acc2[i][j], ad, b2[j]);
            }
        }
        __syncthreads();
    }

#pragma unroll
    for (int i = 0; i < 8; i++) {
        int r = brow + ty * 8 + i;
        if (r < M) {
            float* cp = C + (size_t)r * N + bcol + tx * 8;
            float2 p0 = unpack_f32x2(acc2[i][0]);
            float2 p1 = unpack_f32x2(acc2[i][1]);
            float2 p2 = unpack_f32x2(acc2[i][2]);
            float2 p3 = unpack_f32x2(acc2[i][3]);
            *reinterpret_cast<float4*>(cp)     = make_float4(p0.x, p0.y, p1.x, p1.y);
            *reinterpret_cast<float4*>(cp + 4) = make_float4(p2.x, p2.y, p3.x, p3.y);
        }
    }
}

// ---------------- attention coefficients: as[n,h] = <h[n,h,:], a_src[h,:]> ----------------
__global__ void k_attn(const float* __restrict__ hfeat,
                       const float* __restrict__ a_src, const float* __restrict__ a_dst,
                       float* __restrict__ as, float* __restrict__ ad, int n)
{
    int w = (blockIdx.x * blockDim.x + threadIdx.x) >> 5;
    int lane = threadIdx.x & 31;
    if (w >= n) return;
    const float* hp = hfeat + (size_t)w * FF;
#pragma unroll
    for (int h = 0; h < HH; h++) {
        float ps = 0.f, pd = 0.f;
#pragma unroll
        for (int c = 0; c < 128; c += 32) {
            float hv = hp[h * 128 + c + lane];
            ps = fmaf(hv, a_src[h * 128 + c + lane], ps);
            pd = fmaf(hv, a_dst[h * 128 + c + lane], pd);
        }
#pragma unroll
        for (int off = 16; off; off >>= 1) {
            ps += __shfl_xor_sync(0xffffffffu, ps, off);
            pd += __shfl_xor_sync(0xffffffffu, pd, off);
        }
        if (lane == 0) { as[w * HH + h] = ps; ad[w * HH + h] = pd; }
    }
}

__device__ __forceinline__ float lrelu(float z) { return z > 0.f ? z : SLOPE * z; }
__device__ __forceinline__ float sel4(float4 a, int h) {
    float v = a.x;
    if (h == 1) v = a.y;
    if (h == 2) v = a.z;
    if (h == 3) v = a.w;
    return v;
}

// ---------------- per-dst aggregation with segment softmax ----------------
// one warp per dst node; 3 passes: max, denom, weighted feature sum.
template <bool MEAN>
__global__ __launch_bounds__(256)
void k_agg(const float* __restrict__ hfeat, const float* __restrict__ as,
           const float* __restrict__ ad, const float* __restrict__ bias,
           float* __restrict__ out, int n)
{
    int w = (blockIdx.x * blockDim.x + threadIdx.x) >> 5;
    if (w >= n) return;
    int lane = threadIdx.x & 31;
    int start = g_rowptr[w], end = g_rowptr[w + 1];

    float4 adv = *reinterpret_cast<const float4*>(ad + (size_t)w * 4);

    // pass 1: per-head max
    float m0 = -3.4e38f, m1 = -3.4e38f, m2 = -3.4e38f, m3 = -3.4e38f;
    for (int j = start + lane; j < end; j += 32) {
        int s = g_srcsorted[j];
        float4 a = *reinterpret_cast<const float4*>(as + (size_t)s * 4);
        m0 = fmaxf(m0, lrelu(a.x + adv.x));
        m1 = fmaxf(m1, lrelu(a.y + adv.y));
        m2 = fmaxf(m2, lrelu(a.z + adv.z));
        m3 = fmaxf(m3, lrelu(a.w + adv.w));
    }
#pragma unroll
    for (int off = 16; off; off >>= 1) {
        m0 = fmaxf(m0, __shfl_xor_sync(0xffffffffu, m0, off));
        m1 = fmaxf(m1, __shfl_xor_sync(0xffffffffu, m1, off));
        m2 = fmaxf(m2, __shfl_xor_sync(0xffffffffu, m2, off));
        m3 = fmaxf(m3, __shfl_xor_sync(0xffffffffu, m3, off));
    }

    // pass 2: per-head sum of exp
    float d0 = 0.f, d1 = 0.f, d2 = 0.f, d3 = 0.f;
    for (int j = start + lane; j < end; j += 32) {
        int s = g_srcsorted[j];
        float4 a = *reinterpret_cast<const float4*>(as + (size_t)s * 4);
        d0 += __expf(lrelu(a.x + adv.x) - m0);
        d1 += __expf(lrelu(a.y + adv.y) - m1);
        d2 += __expf(lrelu(a.z + adv.z) - m2);
        d3 += __expf(lrelu(a.w + adv.w) - m3);
    }
#pragma unroll
    for (int off = 16; off; off >>= 1) {
        d0 += __shfl_xor_sync(0xffffffffu, d0, off);
        d1 += __shfl_xor_sync(0xffffffffu, d1, off);
        d2 += __shfl_xor_sync(0xffffffffu, d2, off);
        d3 += __shfl_xor_sync(0xffffffffu, d3, off);
    }
    float i0 = 1.f / (d0 + 1e-16f);
    float i1 = 1.f / (d1 + 1e-16f);
    float i2 = 1.f / (d2 + 1e-16f);
    float i3 = 1.f / (d3 + 1e-16f);

    // pass 3: weighted sum of features. Lane owns 16 contiguous channels
    // c_full = lane*16 + {0..15}; head = lane>>3 (16 | 128 so a lane never straddles heads).
    const int hsel = lane >> 3;
    const float mm = sel4(make_float4(m0, m1, m2, m3), hsel);
    const float ii = sel4(make_float4(i0, i1, i2, i3), hsel);
    const float aD = sel4(adv, hsel);

    float4 acc[4];
#pragma unroll
    for (int k = 0; k < 4; k++) acc[k] = make_float4(0.f, 0.f, 0.f, 0.f);

    for (int j = start; j < end; j++) {
        int s = g_srcsorted[j];
        float4 a = *reinterpret_cast<const float4*>(as + (size_t)s * 4);
        float wgt = __expf(lrelu(sel4(a, hsel) + aD) - mm) * ii;
        const float4* hp4 = reinterpret_cast<const float4*>(hfeat + (size_t)s * FF) + lane * 4;
#pragma unroll
        for (int k = 0; k < 4; k++) {
            float4 v = hp4[k];
            acc[k].x = fmaf(wgt, v.x, acc[k].x);
            acc[k].y = fmaf(wgt, v.y, acc[k].y);
            acc[k].z = fmaf(wgt, v.z, acc[k].z);
            acc[k].w = fmaf(wgt, v.w, acc[k].w);
        }
    }

    if (!MEAN) {
        float4* op = reinterpret_cast<float4*>(out + (size_t)w * FF);
        const float4* bp = reinterpret_cast<const float4*>(bias);
#pragma unroll
        for (int k = 0; k < 4; k++) {
            float4 b4 = bp[lane * 4 + k];
            float4 v = acc[k];
            v.x += b4.x; v.y += b4.y; v.z += b4.z; v.w += b4.w;
            op[lane * 4 + k] = v;
        }
    } else {
        // mean over heads: sum lanes {l, l^8, l^16, l^24}, lanes 0..7 write 128 channels
#pragma unroll
        for (int k = 0; k < 4; k++) {
            acc[k].x += __shfl_xor_sync(0xffffffffu, acc[k].x, 8);
            acc[k].y += __shfl_xor_sync(0xffffffffu, acc[k].y, 8);
            acc[k].z += __shfl_xor_sync(0xffffffffu, acc[k].z, 8);
            acc[k].w += __shfl_xor_sync(0xffffffffu, acc[k].w, 8);
            acc[k].x += __shfl_xor_sync(0xffffffffu, acc[k].x, 16);
            acc[k].y += __shfl_xor_sync(0xffffffffu, acc[k].y, 16);
            acc[k].z += __shfl_xor_sync(0xffffffffu, acc[k].z, 16);
            acc[k].w += __shfl_xor_sync(0xffffffffu, acc[k].w, 16);
        }
        if (lane < 8) {
            float4* op = reinterpret_cast<float4*>(out + (size_t)w * COUT);
            const float4* bp = reinterpret_cast<const float4*>(bias);
#pragma unroll
            for (int k = 0; k < 4; k++) {
                float4 b4 = bp[lane * 4 + k];
                float4 v = acc[k];
                v.x = 0.25f * v.x + b4.x; v.y = 0.25f * v.y + b4.y;
                v.z = 0.25f * v.z + b4.z; v.w = 0.25f * v.w + b4.w;
                op[lane * 4 + k] = v;
            }
        }
    }
}

// ---------------- host ----------------
extern "C" void kernel_launch(void* const* d_in, const int* in_sizes, int n_in,
                              void* d_out, int out_size)
{
    const float* x      = (const float*)d_in[0];
    const int*   ei     = (const int*)d_in[1];
    const float* W1     = (const float*)d_in[2];
    const float* a_src1 = (const float*)d_in[3];
    const float* a_dst1 = (const float*)d_in[4];
    const float* b1     = (const float*)d_in[5];
    const float* W2     = (const float*)d_in[6];
    const float* a_src2 = (const float*)d_in[7];
    const float* a_dst2 = (const float*)d_in[8];
    const float* b2     = (const float*)d_in[9];

    const int N = in_sizes[0] / CIN;
    const int E = in_sizes[1] / 2;

    void *p_h1, *p_agg1, *p_h2, *p_as1, *p_ad1, *p_as2, *p_ad2;
    cudaGetSymbolAddress(&p_h1,  g_h1);
    cudaGetSymbolAddress(&p_agg1, g_agg1);
    cudaGetSymbolAddress(&p_h2,  g_h2);
    cudaGetSymbolAddress(&p_as1, g_as1);
    cudaGetSymbolAddress(&p_ad1, g_ad1);
    cudaGetSymbolAddress(&p_as2, g_as2);
    cudaGetSymbolAddress(&p_ad2, g_ad2);
    float* h1   = (float*)p_h1;
    float* agg1 = (float*)p_agg1;
    float* h2   = (float*)p_h2;
    float* as1  = (float*)p_as1;
    float* ad1  = (float*)p_ad1;
    float* as2  = (float*)p_as2;
    float* ad2  = (float*)p_ad2;
    float* out  = (float*)d_out;

    // CSR build (deterministic work every call)
    k_initcount<<<(N + 255) / 256, 256>>>(N);
    k_count<<<(E + 255) / 256, 256>>>(ei, E);
    k_scan<<<1, 1024>>>(N);
    k_scatter<<<(E + N + 255) / 256, 256>>>(ei, E, N);

    const int warpsGrid = (N * 32 + 255) / 256;

    // layer 1
    dim3 g1(FF / 128, (N + 127) / 128);
    k_sgemm<false><<<g1, 256>>>(x, W1, h1, N, FF, CIN);
    k_attn<<<warpsGrid, 256>>>(h1, a_src1, a_dst1, as1, ad1, N);
    k_agg<false><<<warpsGrid, 256>>>(h1, as1, ad1, b1, agg1, N);

    // layer 2 (ReLU fused into GEMM2's A-load)
    dim3 g2(FF / 128, (N + 127) / 128);
    k_sgemm<true><<<g2, 256>>>(agg1, W2, h2, N, FF, FF);
    k_attn<<<warpsGrid, 256>>>(h2, a_src2, a_dst2, as2, ad2, N);
    k_agg<true><<<warpsGrid, 256>>>(h2, as2, ad2, b2, out, N);
}

// round 9
// speedup vs baseline: 1.6880x; 1.5783x over previous
#include <cuda_runtime.h>
#include <cuda_fp16.h>
#include <cstdint>

// Problem constants (fixed by the dataset)
#define NN   10000
#define EE   320000
#define HH   4
#define CIN  256
#define FF   512          // H*HID = H*OUT = per-node feature width in both layers
#define COUT 128
#define SLOPE 0.2f

// ---------------- scratch (static device globals; no allocation) ----------------
__device__ __half g_hf1[NN * FF];     // layer-1 features (fp16 copy for gather)
__device__ __half g_hf2[NN * FF];     // layer-2 features
__device__ float g_agg1[NN * FF];
__device__ float g_as1[NN * HH];
__device__ float g_ad1[NN * HH];
__device__ float g_as2[NN * HH];
__device__ float g_ad2[NN * HH];
__device__ int   g_counts[NN];
__device__ int   g_rowptr[NN + 1];
__device__ int   g_cursor[NN];
__device__ int   g_srcsorted[EE + NN];

// ---------------- CSR build ----------------
__global__ void k_initcount(int n) {
    int i = blockIdx.x * blockDim.x + threadIdx.x;
    if (i < n) g_counts[i] = 1;   // self loop
}

__global__ void k_count(const int* __restrict__ ei, int E) {
    int i = blockIdx.x * blockDim.x + threadIdx.x;
    if (i < E) atomicAdd(&g_counts[ei[E + i]], 1);
}

// single-block exclusive scan of g_counts -> g_rowptr, g_cursor
__global__ void k_scan(int n) {
    __shared__ int sb[1024];
    int tid = threadIdx.x;
    int per = (n + 1023) >> 10;
    int base = tid * per;
    int sum = 0;
    for (int i = 0; i < per; i++) {
        int idx = base + i;
        if (idx < n) sum += g_counts[idx];
    }
    sb[tid] = sum;
    __syncthreads();
    for (int off = 1; off < 1024; off <<= 1) {
        int v = (tid >= off) ? sb[tid - off] : 0;
        __syncthreads();
        sb[tid] += v;
        __syncthreads();
    }
    int run = sb[tid] - sum;   // exclusive prefix
    for (int i = 0; i < per; i++) {
        int idx = base + i;
        if (idx < n) {
            g_rowptr[idx] = run;
            g_cursor[idx] = run;
            run += g_counts[idx];
        }
    }
    if (tid == 1023) g_rowptr[n] = sb[1023];
}

__global__ void k_scatter(const int* __restrict__ ei, int E, int n) {
    int i = blockIdx.x * blockDim.x + threadIdx.x;
    int total = E + n;
    if (i >= total) return;
    int s, d;
    if (i < E) { s = ei[i]; d = ei[E + i]; }
    else       { s = i - E; d = s; }
    int pos = atomicAdd(&g_cursor[d], 1);
    g_srcsorted[pos] = s;
}

// ---------------- tf32 helpers ----------------
__device__ __forceinline__ void tf32split(float v, float& hi, float& lo) {
    uint32_t h;
    asm("cvt.rna.tf32.f32 %0, %1;" : "=r"(h) : "f"(v));
    hi = __uint_as_float(h);
    float r = v - hi;
    uint32_t l;
    asm("cvt.rna.tf32.f32 %0, %1;" : "=r"(l) : "f"(r));
    lo = __uint_as_float(l);
}

__device__ __forceinline__ void mma_tf32(float* d, const uint32_t* a, const uint32_t* b) {
    asm volatile(
        "mma.sync.aligned.m16n8k8.row.col.f32.tf32.tf32.f32 "
        "{%0,%1,%2,%3}, {%4,%5,%6,%7}, {%8,%9}, {%0,%1,%2,%3};"
        : "+f"(d[0]), "+f"(d[1]), "+f"(d[2]), "+f"(d[3])
        : "r"(a[0]), "r"(a[1]), "r"(a[2]), "r"(a[3]), "r"(b[0]), "r"(b[1]));
}

// ---------------- fused GEMM + attention-coefficient kernel ----------------
// C(tile) = op(A)[M,K] @ W[K,512] on tensor cores (3xTF32). Each CTA computes a
// 128x128 tile = (128 rows) x (one full head). Epilogue writes C as fp16 and the
// per-node attention dots as[row][head], ad[row][head] (no separate k_attn pass).
// Warp layout: 8 warps in 2x4 grid; warp tile 64x32 = 4x4 m16n8 mma tiles.
#define ASTRIDE 12
#define BSTRIDE 132

template <bool RELU_A>
__global__ __launch_bounds__(256)
void k_gemm_attn(const float* __restrict__ A, const float* __restrict__ W,
                 __half* __restrict__ hf,
                 float* __restrict__ as, float* __restrict__ ad,
                 const float* __restrict__ a_src, const float* __restrict__ a_dst,
                 int M, int K)
{
    __shared__ float sA[2][2][128 * ASTRIDE];   // [stage][hi/lo]
    __shared__ float sB[2][2][8 * BSTRIDE];
    __shared__ float sred[2][128][4];           // [as/ad][row][wn]

    const int tid  = threadIdx.x;
    const int wid  = tid >> 5;
    const int lane = tid & 31;
    const int g    = lane >> 2;     // 0..7
    const int tg   = lane & 3;      // 0..3
    const int wm   = wid >> 2;      // 0..1
    const int wn   = wid & 3;       // 0..3
    const int mb   = wm * 64;
    const int nb   = wn * 32;

    const int head = blockIdx.x;
    const int brow = blockIdx.y * 128;

    // staging coords
    const int aRow = tid >> 1;           // 0..127
    const int aCol = (tid & 1) * 4;      // 0 or 4
    const int bRow = tid >> 5;           // 0..7
    const int bCol = (tid & 31) * 4;     // 0..124
    const bool okA = (brow + aRow) < M;
    const float* Abase = A + (size_t)(brow + aRow) * K + aCol;
    const float* Bbase = W + (size_t)bRow * FF + head * 128 + bCol;

    float acc[4][4][4];
#pragma unroll
    for (int mt = 0; mt < 4; mt++)
#pragma unroll
        for (int nt = 0; nt < 4; nt++)
#pragma unroll
            for (int q = 0; q < 4; q++) acc[mt][nt][q] = 0.f;

    // preload first K-chunk
    float4 av = make_float4(0.f, 0.f, 0.f, 0.f);
    if (okA) av = *reinterpret_cast<const float4*>(Abase);
    float4 bv = *reinterpret_cast<const float4*>(Bbase);

    const int nk = K >> 3;
    for (int t = 0; t < nk; t++) {
        const int cur = t & 1;
        // split + store staged chunk
        {
            float4 a = av;
            if (RELU_A) {
                a.x = fmaxf(a.x, 0.f); a.y = fmaxf(a.y, 0.f);
                a.z = fmaxf(a.z, 0.f); a.w = fmaxf(a.w, 0.f);
            }
            float h0, l0, h1, l1, h2, l2, h3, l3;
            tf32split(a.x, h0, l0); tf32split(a.y, h1, l1);
            tf32split(a.z, h2, l2); tf32split(a.w, h3, l3);
            float* dh = &sA[cur][0][aRow * ASTRIDE + aCol];
            float* dl = &sA[cur][1][aRow * ASTRIDE + aCol];
            dh[0] = h0; dh[1] = h1; dh[2] = h2; dh[3] = h3;
            dl[0] = l0; dl[1] = l1; dl[2] = l2; dl[3] = l3;

            float4 b = bv;
            tf32split(b.x, h0, l0); tf32split(b.y, h1, l1);
            tf32split(b.z, h2, l2); tf32split(b.w, h3, l3);
            float* eh = &sB[cur][0][bRow * BSTRIDE + bCol];
            float* el = &sB[cur][1][bRow * BSTRIDE + bCol];
            eh[0] = h0; eh[1] = h1; eh[2] = h2; eh[3] = h3;
            el[0] = l0; el[1] = l1; el[2] = l2; el[3] = l3;
        }
        __syncthreads();

        // prefetch next chunk
        if (t + 1 < nk) {
            if (okA) av = *reinterpret_cast<const float4*>(Abase + (t + 1) * 8);
            bv = *reinterpret_cast<const float4*>(Bbase + (size_t)(t + 1) * 8 * FF);
        }

        // B fragments (col-major k8 x n8): b0 = B[tg][n], b1 = B[tg+4][n]
        uint32_t bh[4][2], bl[4][2];
#pragma unroll
        for (int nt = 0; nt < 4; nt++) {
            int nc = nb + nt * 8 + g;
            bh[nt][0] = __float_as_uint(sB[cur][0][tg * BSTRIDE + nc]);
            bh[nt][1] = __float_as_uint(sB[cur][0][(tg + 4) * BSTRIDE + nc]);
            bl[nt][0] = __float_as_uint(sB[cur][1][tg * BSTRIDE + nc]);
            bl[nt][1] = __float_as_uint(sB[cur][1][(tg + 4) * BSTRIDE + nc]);
        }
#pragma unroll
        for (int mt = 0; mt < 4; mt++) {
            int r0 = mb + mt * 16 + g;
            uint32_t ah[4], al[4];
            ah[0] = __float_as_uint(sA[cur][0][r0 * ASTRIDE + tg]);
            ah[1] = __float_as_uint(sA[cur][0][(r0 + 8) * ASTRIDE + tg]);
            ah[2] = __float_as_uint(sA[cur][0][r0 * ASTRIDE + tg + 4]);
            ah[3] = __float_as_uint(sA[cur][0][(r0 + 8) * ASTRIDE + tg + 4]);
            al[0] = __float_as_uint(sA[cur][1][r0 * ASTRIDE + tg]);
            al[1] = __float_as_uint(sA[cur][1][(r0 + 8) * ASTRIDE + tg]);
            al[2] = __float_as_uint(sA[cur][1][r0 * ASTRIDE + tg + 4]);
            al[3] = __float_as_uint(sA[cur][1][(r0 + 8) * ASTRIDE + tg + 4]);
#pragma unroll
            for (int nt = 0; nt < 4; nt++) {
                mma_tf32(acc[mt][nt], ah, bh[nt]);   // hi*hi
                mma_tf32(acc[mt][nt], al, bh[nt]);   // lo*hi
                mma_tf32(acc[mt][nt], ah, bl[nt]);   // hi*lo
            }
        }
        __syncthreads();
    }

    // ---- epilogue: fp16 store + fused attention dots ----
    // lane owns cols col0/col1 = nb + nt*8 + 2tg (+1) for nt 0..3
    float asv0[4], asv1[4], adv0[4], adv1[4];
#pragma unroll
    for (int nt = 0; nt < 4; nt++) {
        int c = nb + nt * 8 + 2 * tg;
        asv0[nt] = a_src[head * 128 + c];
        asv1[nt] = a_src[head * 128 + c + 1];
        adv0[nt] = a_dst[head * 128 + c];
        adv1[nt] = a_dst[head * 128 + c + 1];
    }

#pragma unroll
    for (int mt = 0; mt < 4; mt++) {
#pragma unroll
        for (int rh = 0; rh < 2; rh++) {
            int rloc = mb + mt * 16 + rh * 8 + g;
            int row  = brow + rloc;
            float ps = 0.f, pd = 0.f;
#pragma unroll
            for (int nt = 0; nt < 4; nt++) {
                float c0 = acc[mt][nt][rh * 2];
                float c1 = acc[mt][nt][rh * 2 + 1];
                ps = fmaf(c0, asv0[nt], fmaf(c1, asv1[nt], ps));
                pd = fmaf(c0, adv0[nt], fmaf(c1, adv1[nt], pd));
                if (row < M) {
                    int col = head * 128 + nb + nt * 8 + 2 * tg;
                    *reinterpret_cast<__half2*>(hf + (size_t)row * FF + col) =
                        __floats2half2_rn(c0, c1);
                }
            }
            // reduce over the 4 tg lanes
            ps += __shfl_xor_sync(0xffffffffu, ps, 1);
            ps += __shfl_xor_sync(0xffffffffu, ps, 2);
            pd += __shfl_xor_sync(0xffffffffu, pd, 1);
            pd += __shfl_xor_sync(0xffffffffu, pd, 2);
            if (tg == 0) {
                sred[0][rloc][wn] = ps;
                sred[1][rloc][wn] = pd;
            }
        }
    }
    __syncthreads();
    if (tid < 128) {
        int row = brow + tid;
        if (row < M) {
            float s = sred[0][tid][0] + sred[0][tid][1] + sred[0][tid][2] + sred[0][tid][3];
            float d = sred[1][tid][0] + sred[1][tid][1] + sred[1][tid][2] + sred[1][tid][3];
            as[row * HH + head] = s;
            ad[row * HH + head] = d;
        }
    }
}

__device__ __forceinline__ float lrelu(float z) { return z > 0.f ? z : SLOPE * z; }
__device__ __forceinline__ float sel4(float4 a, int h) {
    float v = a.x;
    if (h == 1) v = a.y;
    if (h == 2) v = a.z;
    if (h == 3) v = a.w;
    return v;
}

// ---------------- per-dst aggregation with segment softmax ----------------
// one warp per dst node; 3 passes: max, denom, weighted feature sum (fp16 gather).
template <bool MEAN>
__global__ __launch_bounds__(256)
void k_agg(const __half* __restrict__ hfeat, const float* __restrict__ as,
           const float* __restrict__ ad, const float* __restrict__ bias,
           float* __restrict__ out, int n)
{
    int w = (blockIdx.x * blockDim.x + threadIdx.x) >> 5;
    if (w >= n) return;
    int lane = threadIdx.x & 31;
    int start = g_rowptr[w], end = g_rowptr[w + 1];

    float4 adv = *reinterpret_cast<const float4*>(ad + (size_t)w * 4);

    // pass 1: per-head max
    float m0 = -3.4e38f, m1 = -3.4e38f, m2 = -3.4e38f, m3 = -3.4e38f;
    for (int j = start + lane; j < end; j += 32) {
        int s = g_srcsorted[j];
        float4 a = *reinterpret_cast<const float4*>(as + (size_t)s * 4);
        m0 = fmaxf(m0, lrelu(a.x + adv.x));
        m1 = fmaxf(m1, lrelu(a.y + adv.y));
        m2 = fmaxf(m2, lrelu(a.z + adv.z));
        m3 = fmaxf(m3, lrelu(a.w + adv.w));
    }
#pragma unroll
    for (int off = 16; off; off >>= 1) {
        m0 = fmaxf(m0, __shfl_xor_sync(0xffffffffu, m0, off));
        m1 = fmaxf(m1, __shfl_xor_sync(0xffffffffu, m1, off));
        m2 = fmaxf(m2, __shfl_xor_sync(0xffffffffu, m2, off));
        m3 = fmaxf(m3, __shfl_xor_sync(0xffffffffu, m3, off));
    }

    // pass 2: per-head sum of exp
    float d0 = 0.f, d1 = 0.f, d2 = 0.f, d3 = 0.f;
    for (int j = start + lane; j < end; j += 32) {
        int s = g_srcsorted[j];
        float4 a = *reinterpret_cast<const float4*>(as + (size_t)s * 4);
        d0 += __expf(lrelu(a.x + adv.x) - m0);
        d1 += __expf(lrelu(a.y + adv.y) - m1);
        d2 += __expf(lrelu(a.z + adv.z) - m2);
        d3 += __expf(lrelu(a.w + adv.w) - m3);
    }
#pragma unroll
    for (int off = 16; off; off >>= 1) {
        d0 += __shfl_xor_sync(0xffffffffu, d0, off);
        d1 += __shfl_xor_sync(0xffffffffu, d1, off);
        d2 += __shfl_xor_sync(0xffffffffu, d2, off);
        d3 += __shfl_xor_sync(0xffffffffu, d3, off);
    }
    float i0 = 1.f / (d0 + 1e-16f);
    float i1 = 1.f / (d1 + 1e-16f);
    float i2 = 1.f / (d2 + 1e-16f);
    float i3 = 1.f / (d3 + 1e-16f);

    // pass 3: weighted fp16 feature gather. Lane owns 16 contiguous channels
    // (lane*16..+15); head = lane>>3 (a lane never straddles heads).
    const int hsel = lane >> 3;
    const float mm = sel4(make_float4(m0, m1, m2, m3), hsel);
    const float ii = sel4(make_float4(i0, i1, i2, i3), hsel);
    const float aD = sel4(adv, hsel);

    float4 acc[4];
#pragma unroll
    for (int k = 0; k < 4; k++) acc[k] = make_float4(0.f, 0.f, 0.f, 0.f);

    for (int j = start; j < end; j++) {
        int s = g_srcsorted[j];
        float4 a = *reinterpret_cast<const float4*>(as + (size_t)s * 4);
        float wgt = __expf(lrelu(sel4(a, hsel) + aD) - mm) * ii;
        const uint4* hp = reinterpret_cast<const uint4*>(hfeat + (size_t)s * FF) + lane * 2;
        uint4 q0 = hp[0];
        uint4 q1 = hp[1];
        const __half2* ph = reinterpret_cast<const __half2*>(&q0);
#pragma unroll
        for (int k = 0; k < 2; k++) {
            float2 fa = __half22float2(ph[2 * k]);
            float2 fb = __half22float2(ph[2 * k + 1]);
            acc[k].x = fmaf(wgt, fa.x, acc[k].x);
            acc[k].y = fmaf(wgt, fa.y, acc[k].y);
            acc[k].z = fmaf(wgt, fb.x, acc[k].z);
            acc[k].w = fmaf(wgt, fb.y, acc[k].w);
        }
        const __half2* qh = reinterpret_cast<const __half2*>(&q1);
#pragma unroll
        for (int k = 0; k < 2; k++) {
            float2 fa = __half22float2(qh[2 * k]);
            float2 fb = __half22float2(qh[2 * k + 1]);
            acc[k + 2].x = fmaf(wgt, fa.x, acc[k + 2].x);
            acc[k + 2].y = fmaf(wgt, fa.y, acc[k + 2].y);
            acc[k + 2].z = fmaf(wgt, fb.x, acc[k + 2].z);
            acc[k + 2].w = fmaf(wgt, fb.y, acc[k + 2].w);
        }
    }

    if (!MEAN) {
        float4* op = reinterpret_cast<float4*>(out + (size_t)w * FF);
        const float4* bp = reinterpret_cast<const float4*>(bias);
#pragma unroll
        for (int k = 0; k < 4; k++) {
            float4 b4 = bp[lane * 4 + k];
            float4 v = acc[k];
            v.x += b4.x; v.y += b4.y; v.z += b4.z; v.w += b4.w;
            op[lane * 4 + k] = v;
        }
    } else {
        // mean over heads: sum lanes {l, l^8, l^16, l^24}, lanes 0..7 write 128 channels
#pragma unroll
        for (int k = 0; k < 4; k++) {
            acc[k].x += __shfl_xor_sync(0xffffffffu, acc[k].x, 8);
            acc[k].y += __shfl_xor_sync(0xffffffffu, acc[k].y, 8);
            acc[k].z += __shfl_xor_sync(0xffffffffu, acc[k].z, 8);
            acc[k].w += __shfl_xor_sync(0xffffffffu, acc[k].w, 8);
            acc[k].x += __shfl_xor_sync(0xffffffffu, acc[k].x, 16);
            acc[k].y += __shfl_xor_sync(0xffffffffu, acc[k].y, 16);
            acc[k].z += __shfl_xor_sync(0xffffffffu, acc[k].z, 16);
            acc[k].w += __shfl_xor_sync(0xffffffffu, acc[k].w, 16);
        }
        if (lane < 8) {
            float4* op = reinterpret_cast<float4*>(out + (size_t)w * COUT);
            const float4* bp = reinterpret_cast<const float4*>(bias);
#pragma unroll
            for (int k = 0; k < 4; k++) {
                float4 b4 = bp[lane * 4 + k];
                float4 v = acc[k];
                v.x = 0.25f * v.x + b4.x; v.y = 0.25f * v.y + b4.y;
                v.z = 0.25f * v.z + b4.z; v.w = 0.25f * v.w + b4.w;
                op[lane * 4 + k] = v;
            }
        }
    }
}

// ---------------- host ----------------
extern "C" void kernel_launch(void* const* d_in, const int* in_sizes, int n_in,
                              void* d_out, int out_size)
{
    const float* x      = (const float*)d_in[0];
    const int*   ei     = (const int*)d_in[1];
    const float* W1     = (const float*)d_in[2];
    const float* a_src1 = (const float*)d_in[3];
    const float* a_dst1 = (const float*)d_in[4];
    const float* b1     = (const float*)d_in[5];
    const float* W2     = (const float*)d_in[6];
    const float* a_src2 = (const float*)d_in[7];
    const float* a_dst2 = (const float*)d_in[8];
    const float* b2     = (const float*)d_in[9];

    const int N = in_sizes[0] / CIN;
    const int E = in_sizes[1] / 2;

    void *p_hf1, *p_hf2, *p_agg1, *p_as1, *p_ad1, *p_as2, *p_ad2;
    cudaGetSymbolAddress(&p_hf1, g_hf1);
    cudaGetSymbolAddress(&p_hf2, g_hf2);
    cudaGetSymbolAddress(&p_agg1, g_agg1);
    cudaGetSymbolAddress(&p_as1, g_as1);
    cudaGetSymbolAddress(&p_ad1, g_ad1);
    cudaGetSymbolAddress(&p_as2, g_as2);
    cudaGetSymbolAddress(&p_ad2, g_ad2);
    __half* hf1 = (__half*)p_hf1;
    __half* hf2 = (__half*)p_hf2;
    float* agg1 = (float*)p_agg1;
    float* as1  = (float*)p_as1;
    float* ad1  = (float*)p_ad1;
    float* as2  = (float*)p_as2;
    float* ad2  = (float*)p_ad2;
    float* out  = (float*)d_out;

    // CSR build (deterministic work every call)
    k_initcount<<<(N + 255) / 256, 256>>>(N);
    k_count<<<(E + 255) / 256, 256>>>(ei, E);
    k_scan<<<1, 1024>>>(N);
    k_scatter<<<(E + N + 255) / 256, 256>>>(ei, E, N);

    const int warpsGrid = (N * 32 + 255) / 256;
    const dim3 gg(HH, (N + 127) / 128);   // 4 heads x 79 row tiles

    // layer 1: fused GEMM + attn dots, then aggregate (+b1)
    k_gemm_attn<false><<<gg, 256>>>(x, W1, hf1, as1, ad1, a_src1, a_dst1, N, CIN);
    k_agg<false><<<warpsGrid, 256>>>(hf1, as1, ad1, b1, agg1, N);

    // layer 2: ReLU fused into GEMM2's A-side split; head-mean + b2 in agg
    k_gemm_attn<true><<<gg, 256>>>(agg1, W2, hf2, as2, ad2, a_src2, a_dst2, N, FF);
    k_agg<true><<<warpsGrid, 256>>>(hf2, as2, ad2, b2, out, N);
}

// round 13
// speedup vs baseline: 1.9144x; 1.1341x over previous
#include <cuda_runtime.h>
#include <cuda_fp16.h>
#include <cstdint>

// Problem constants (fixed by the dataset)
#define NN   10000
#define EE   320000
#define HH   4
#define CIN  256
#define FF   512          // H*HID = H*OUT = per-node feature width in both layers
#define COUT 128
#define SLOPE 0.2f

// ---------------- scratch (static device globals; no allocation) ----------------
__device__ __half g_hf1[NN * FF];     // layer-1 features (fp16 copy for gather)
__device__ __half g_hf2[NN * FF];     // layer-2 features
__device__ float g_agg1[NN * FF];
__device__ float g_as1[NN * HH];
__device__ float g_ad1[NN * HH];
__device__ float g_as2[NN * HH];
__device__ float g_ad2[NN * HH];
__device__ int   g_counts[NN];
__device__ int   g_rowptr[NN + 1];
__device__ int   g_cursor[NN];
__device__ int   g_srcsorted[EE + NN];

// ---------------- CSR build ----------------
__global__ void k_count(const int* __restrict__ ei, int E) {
    int i = blockIdx.x * blockDim.x + threadIdx.x;
    if (i < E) atomicAdd(&g_counts[ei[E + i]], 1);
}

// single-block exclusive scan of (g_counts[i]+1) -> g_rowptr, g_cursor
// (+1 = the self loop; g_counts arrives zero-initialized via memset)
__global__ void k_scan(int n) {
    __shared__ int sb[1024];
    int tid = threadIdx.x;
    int per = (n + 1023) >> 10;
    int base = tid * per;
    int sum = 0;
    for (int i = 0; i < per; i++) {
        int idx = base + i;
        if (idx < n) sum += g_counts[idx] + 1;
    }
    sb[tid] = sum;
    __syncthreads();
    for (int off = 1; off < 1024; off <<= 1) {
        int v = (tid >= off) ? sb[tid - off] : 0;
        __syncthreads();
        sb[tid] += v;
        __syncthreads();
    }
    int run = sb[tid] - sum;   // exclusive prefix
    for (int i = 0; i < per; i++) {
        int idx = base + i;
        if (idx < n) {
            g_rowptr[idx] = run;
            g_cursor[idx] = run;
            run += g_counts[idx] + 1;
        }
    }
    if (tid == 1023) g_rowptr[n] = sb[1023];
}

__global__ void k_scatter(const int* __restrict__ ei, int E, int n) {
    int i = blockIdx.x * blockDim.x + threadIdx.x;
    int total = E + n;
    if (i >= total) return;
    int s, d;
    if (i < E) { s = ei[i]; d = ei[E + i]; }
    else       { s = i - E; d = s; }
    int pos = atomicAdd(&g_cursor[d], 1);
    g_srcsorted[pos] = s;
}

// ---------------- fp16 split helpers ----------------
// v = hi + lo in fp16 pieces (~22 mantissa bits total); products accumulated fp32.
__device__ __forceinline__ void f16split(float v, __half& hi, __half& lo) {
    hi = __float2half_rn(v);
    lo = __float2half_rn(v - __half2float(hi));
}

__device__ __forceinline__ void mma_f16(float* d, const uint32_t* a, const uint32_t* b) {
    asm volatile(
        "mma.sync.aligned.m16n8k16.row.col.f32.f16.f16.f32 "
        "{%0,%1,%2,%3}, {%4,%5,%6,%7}, {%8,%9}, {%0,%1,%2,%3};"
        : "+f"(d[0]), "+f"(d[1]), "+f"(d[2]), "+f"(d[3])
        : "r"(a[0]), "r"(a[1]), "r"(a[2]), "r"(a[3]), "r"(b[0]), "r"(b[1]));
}

// ---------------- fused GEMM + attention-coefficient kernel ----------------
// C(tile) = op(A)[M,K] @ W[K,512] via 3x fp16-split m16n8k16 (fp32 accum).
// Each CTA: 128 rows x one head (128 cols). 8 warps in 2x4; warp tile 64x32.
// SMEM layout packs K-adjacent fp16 pairs in uint32 so each fragment piece is
// one 32-bit LDS: sA[row][j] = {A[row][2j],A[row][2j+1]}, sB[n][j] = {B[2j][n],B[2j+1][n]}.
#define AJ 9      // padded uint32 row stride for A (8 pairs + 1)
#define BJ 9      // padded uint32 row stride for B

template <bool RELU_A>
__global__ __launch_bounds__(256)
void k_gemm_attn(const float* __restrict__ A, const float* __restrict__ W,
                 __half* __restrict__ hf,
                 float* __restrict__ as, float* __restrict__ ad,
                 const float* __restrict__ a_src, const float* __restrict__ a_dst,
                 int M, int K)
{
    __shared__ uint32_t sA[2][2][128 * AJ];   // [stage][hi/lo]
    __shared__ uint32_t sB[2][2][128 * BJ];
    __shared__ float sred[2][128][4];         // [as/ad][row][wn]

    const int tid  = threadIdx.x;
    const int wid  = tid >> 5;
    const int lane = tid & 31;
    const int g    = lane >> 2;     // 0..7
    const int tg   = lane & 3;      // 0..3
    const int wm   = wid >> 2;      // 0..1
    const int wn   = wid & 3;       // 0..3
    const int mb   = wm * 64;
    const int nb   = wn * 32;

    const int head = blockIdx.x;
    const int brow = blockIdx.y * 128;

    // staging coords: A -> thread owns row aRow, K-eights aK8..aK8+7 of each chunk
    const int aRow = tid >> 1;            // 0..127
    const int aK8  = (tid & 1) * 8;       // 0 or 8
    // B -> thread owns k-row bK, 8 n columns nC..nC+7
    const int bK   = tid >> 4;            // 0..15
    const int nC   = (tid & 15) * 8;      // 0..120

    const bool okA = (brow + aRow) < M;
    const float* Abase = A + (size_t)(brow + aRow) * K + aK8;
    const float* Bbase = W + (size_t)bK * FF + head * 128 + nC;

    float acc[4][4][4];
#pragma unroll
    for (int mt = 0; mt < 4; mt++)
#pragma unroll
        for (int nt = 0; nt < 4; nt++)
#pragma unroll
            for (int q = 0; q < 4; q++) acc[mt][nt][q] = 0.f;

    // preload first K-chunk (16 wide)
    float4 av0 = make_float4(0.f,0.f,0.f,0.f), av1 = av0;
    if (okA) {
        av0 = *reinterpret_cast<const float4*>(Abase);
        av1 = *reinterpret_cast<const float4*>(Abase + 4);
    }
    float4 bv0 = *reinterpret_cast<const float4*>(Bbase);
    float4 bv1 = *reinterpret_cast<const float4*>(Bbase + 4);

    const int nk = K >> 4;
    for (int t = 0; t < nk; t++) {
        const int cur = t & 1;
        // ---- split + store staged chunk ----
        {
            float a[8] = {av0.x, av0.y, av0.z, av0.w, av1.x, av1.y, av1.z, av1.w};
            if (RELU_A) {
#pragma unroll
                for (int i = 0; i < 8; i++) a[i] = fmaxf(a[i], 0.f);
            }
            __half h[8], l[8];
#pragma unroll
            for (int i = 0; i < 8; i++) f16split(a[i], h[i], l[i]);
            uint32_t* dh = &sA[cur][0][aRow * AJ + (aK8 >> 1)];
            uint32_t* dl = &sA[cur][1][aRow * AJ + (aK8 >> 1)];
#pragma unroll
            for (int i = 0; i < 4; i++) {
                __half2 ph = __halves2half2(h[2*i], h[2*i+1]);
                __half2 pl = __halves2half2(l[2*i], l[2*i+1]);
                dh[i] = *reinterpret_cast<uint32_t*>(&ph);
                dl[i] = *reinterpret_cast<uint32_t*>(&pl);
            }

            float b[8] = {bv0.x, bv0.y, bv0.z, bv0.w, bv1.x, bv1.y, bv1.z, bv1.w};
            __half* eh = reinterpret_cast<__half*>(&sB[cur][0][0]);
            __half* el = reinterpret_cast<__half*>(&sB[cur][1][0]);
#pragma unroll
            for (int i = 0; i < 8; i++) {
                __half hb, lb;
                f16split(b[i], hb, lb);
                int n = nC + i;
                eh[n * (2 * BJ) + bK] = hb;   // half index: pair j=bK/2, slot bK&1
                el[n * (2 * BJ) + bK] = lb;
            }
        }
        __syncthreads();

        // prefetch next chunk
        if (t + 1 < nk) {
            if (okA) {
                av0 = *reinterpret_cast<const float4*>(Abase + (t + 1) * 16);
                av1 = *reinterpret_cast<const float4*>(Abase + (t + 1) * 16 + 4);
            }
            bv0 = *reinterpret_cast<const float4*>(Bbase + (size_t)(t + 1) * 16 * FF);
            bv1 = *reinterpret_cast<const float4*>(Bbase + (size_t)(t + 1) * 16 * FF + 4);
        }

        // ---- B fragments: b0 = {B[2tg][n],B[2tg+1][n]}, b1 = {B[2tg+8][n],...} ----
        uint32_t bh[4][2], bl[4][2];
#pragma unroll
        for (int nt = 0; nt < 4; nt++) {
            int n = nb + nt * 8 + g;
            bh[nt][0] = sB[cur][0][n * BJ + tg];
            bh[nt][1] = sB[cur][0][n * BJ + tg + 4];
            bl[nt][0] = sB[cur][1][n * BJ + tg];
            bl[nt][1] = sB[cur][1][n * BJ + tg + 4];
        }
#pragma unroll
        for (int mt = 0; mt < 4; mt++) {
            int r0 = mb + mt * 16 + g;
            uint32_t ah[4], al[4];
            ah[0] = sA[cur][0][r0 * AJ + tg];
            ah[1] = sA[cur][0][(r0 + 8) * AJ + tg];
            ah[2] = sA[cur][0][r0 * AJ + tg + 4];
            ah[3] = sA[cur][0][(r0 + 8) * AJ + tg + 4];
            al[0] = sA[cur][1][r0 * AJ + tg];
            al[1] = sA[cur][1][(r0 + 8) * AJ + tg];
            al[2] = sA[cur][1][r0 * AJ + tg + 4];
            al[3] = sA[cur][1][(r0 + 8) * AJ + tg + 4];
#pragma unroll
            for (int nt = 0; nt < 4; nt++) {
                mma_f16(acc[mt][nt], ah, bh[nt]);   // hi*hi
                mma_f16(acc[mt][nt], al, bh[nt]);   // lo*hi
                mma_f16(acc[mt][nt], ah, bl[nt]);   // hi*lo
            }
        }
        __syncthreads();
    }

    // ---- epilogue: fp16 store + fused attention dots ----
    float asv0[4], asv1[4], adv0[4], adv1[4];
#pragma unroll
    for (int nt = 0; nt < 4; nt++) {
        int c = nb + nt * 8 + 2 * tg;
        asv0[nt] = a_src[head * 128 + c];
        asv1[nt] = a_src[head * 128 + c + 1];
        adv0[nt] = a_dst[head * 128 + c];
        adv1[nt] = a_dst[head * 128 + c + 1];
    }

#pragma unroll
    for (int mt = 0; mt < 4; mt++) {
#pragma unroll
        for (int rh = 0; rh < 2; rh++) {
            int rloc = mb + mt * 16 + rh * 8 + g;
            int row  = brow + rloc;
            float ps = 0.f, pd = 0.f;
#pragma unroll
            for (int nt = 0; nt < 4; nt++) {
                float c0 = acc[mt][nt][rh * 2];
                float c1 = acc[mt][nt][rh * 2 + 1];
                ps = fmaf(c0, asv0[nt], fmaf(c1, asv1[nt], ps));
                pd = fmaf(c0, adv0[nt], fmaf(c1, adv1[nt], pd));
                if (row < M) {
                    int col = head * 128 + nb + nt * 8 + 2 * tg;
                    *reinterpret_cast<__half2*>(hf + (size_t)row * FF + col) =
                        __floats2half2_rn(c0, c1);
                }
            }
            ps += __shfl_xor_sync(0xffffffffu, ps, 1);
            ps += __shfl_xor_sync(0xffffffffu, ps, 2);
            pd += __shfl_xor_sync(0xffffffffu, pd, 1);
            pd += __shfl_xor_sync(0xffffffffu, pd, 2);
            if (tg == 0) {
                sred[0][rloc][wn] = ps;
                sred[1][rloc][wn] = pd;
            }
        }
    }
    __syncthreads();
    if (tid < 128) {
        int row = brow + tid;
        if (row < M) {
            float s = sred[0][tid][0] + sred[0][tid][1] + sred[0][tid][2] + sred[0][tid][3];
            float d = sred[1][tid][0] + sred[1][tid][1] + sred[1][tid][2] + sred[1][tid][3];
            as[row * HH + head] = s;
            ad[row * HH + head] = d;
        }
    }
}

__device__ __forceinline__ float lrelu(float z) { return z > 0.f ? z : SLOPE * z; }
__device__ __forceinline__ float sel4(float4 a, int h) {
    float v = a.x;
    if (h == 1) v = a.y;
    if (h == 2) v = a.z;
    if (h == 3) v = a.w;
    return v;
}

// ---------------- per-dst aggregation with segment softmax ----------------
// one warp per dst node; 3 passes: max, denom, weighted feature sum (fp16 gather).
template <bool MEAN>
__global__ __launch_bounds__(256)
void k_agg(const __half* __restrict__ hfeat, const float* __restrict__ as,
           const float* __restrict__ ad, const float* __restrict__ bias,
           float* __restrict__ out, int n)
{
    int w = (blockIdx.x * blockDim.x + threadIdx.x) >> 5;
    if (w >= n) return;
    int lane = threadIdx.x & 31;
    int start = g_rowptr[w], end = g_rowptr[w + 1];

    float4 adv = *reinterpret_cast<const float4*>(ad + (size_t)w * 4);

    // pass 1: per-head max
    float m0 = -3.4e38f, m1 = -3.4e38f, m2 = -3.4e38f, m3 = -3.4e38f;
    for (int j = start + lane; j < end; j += 32) {
        int s = g_srcsorted[j];
        float4 a = *reinterpret_cast<const float4*>(as + (size_t)s * 4);
        m0 = fmaxf(m0, lrelu(a.x + adv.x));
        m1 = fmaxf(m1, lrelu(a.y + adv.y));
        m2 = fmaxf(m2, lrelu(a.z + adv.z));
        m3 = fmaxf(m3, lrelu(a.w + adv.w));
    }
#pragma unroll
    for (int off = 16; off; off >>= 1) {
        m0 = fmaxf(m0, __shfl_xor_sync(0xffffffffu, m0, off));
        m1 = fmaxf(m1, __shfl_xor_sync(0xffffffffu, m1, off));
        m2 = fmaxf(m2, __shfl_xor_sync(0xffffffffu, m2, off));
        m3 = fmaxf(m3, __shfl_xor_sync(0xffffffffu, m3, off));
    }

    // pass 2: per-head sum of exp
    float d0 = 0.f, d1 = 0.f, d2 = 0.f, d3 = 0.f;
    for (int j = start + lane; j < end; j += 32) {
        int s = g_srcsorted[j];
        float4 a = *reinterpret_cast<const float4*>(as + (size_t)s * 4);
        d0 += __expf(lrelu(a.x + adv.x) - m0);
        d1 += __expf(lrelu(a.y + adv.y) - m1);
        d2 += __expf(lrelu(a.z + adv.z) - m2);
        d3 += __expf(lrelu(a.w + adv.w) - m3);
    }
#pragma unroll
    for (int off = 16; off; off >>= 1) {
        d0 += __shfl_xor_sync(0xffffffffu, d0, off);
        d1 += __shfl_xor_sync(0xffffffffu, d1, off);
        d2 += __shfl_xor_sync(0xffffffffu, d2, off);
        d3 += __shfl_xor_sync(0xffffffffu, d3, off);
    }
    float i0 = 1.f / (d0 + 1e-16f);
    float i1 = 1.f / (d1 + 1e-16f);
    float i2 = 1.f / (d2 + 1e-16f);
    float i3 = 1.f / (d3 + 1e-16f);

    // pass 3: weighted fp16 feature gather. Lane owns 16 contiguous channels
    // (lane*16..+15); head = lane>>3 (a lane never straddles heads).
    const int hsel = lane >> 3;
    const float mm = sel4(make_float4(m0, m1, m2, m3), hsel);
    const float ii = sel4(make_float4(i0, i1, i2, i3), hsel);
    const float aD = sel4(adv, hsel);

    float4 acc[4];
#pragma unroll
    for (int k = 0; k < 4; k++) acc[k] = make_float4(0.f, 0.f, 0.f, 0.f);

    for (int j = start; j < end; j++) {
        int s = g_srcsorted[j];
        float4 a = *reinterpret_cast<const float4*>(as + (size_t)s * 4);
        float wgt = __expf(lrelu(sel4(a, hsel) + aD) - mm) * ii;
        const uint4* hp = reinterpret_cast<const uint4*>(hfeat + (size_t)s * FF) + lane * 2;
        uint4 q0 = hp[0];
        uint4 q1 = hp[1];
        const __half2* ph = reinterpret_cast<const __half2*>(&q0);
#pragma unroll
        for (int k = 0; k < 2; k++) {
            float2 fa = __half22float2(ph[2 * k]);
            float2 fb = __half22float2(ph[2 * k + 1]);
            acc[k].x = fmaf(wgt, fa.x, acc[k].x);
            acc[k].y = fmaf(wgt, fa.y, acc[k].y);
            acc[k].z = fmaf(wgt, fb.x, acc[k].z);
            acc[k].w = fmaf(wgt, fb.y, acc[k].w);
        }
        const __half2* qh = reinterpret_cast<const __half2*>(&q1);
#pragma unroll
        for (int k = 0; k < 2; k++) {
            float2 fa = __half22float2(qh[2 * k]);
            float2 fb = __half22float2(qh[2 * k + 1]);
            acc[k + 2].x = fmaf(wgt, fa.x, acc[k + 2].x);
            acc[k + 2].y = fmaf(wgt, fa.y, acc[k + 2].y);
            acc[k + 2].z = fmaf(wgt, fb.x, acc[k + 2].z);
            acc[k + 2].w = fmaf(wgt, fb.y, acc[k + 2].w);
        }
    }

    if (!MEAN) {
        float4* op = reinterpret_cast<float4*>(out + (size_t)w * FF);
        const float4* bp = reinterpret_cast<const float4*>(bias);
#pragma unroll
        for (int k = 0; k < 4; k++) {
            float4 b4 = bp[lane * 4 + k];
            float4 v = acc[k];
            v.x += b4.x; v.y += b4.y; v.z += b4.z; v.w += b4.w;
            op[lane * 4 + k] = v;
        }
    } else {
        // mean over heads: sum lanes {l, l^8, l^16, l^24}, lanes 0..7 write 128 channels
#pragma unroll
        for (int k = 0; k < 4; k++) {
            acc[k].x += __shfl_xor_sync(0xffffffffu, acc[k].x, 8);
            acc[k].y += __shfl_xor_sync(0xffffffffu, acc[k].y, 8);
            acc[k].z += __shfl_xor_sync(0xffffffffu, acc[k].z, 8);
            acc[k].w += __shfl_xor_sync(0xffffffffu, acc[k].w, 8);
            acc[k].x += __shfl_xor_sync(0xffffffffu, acc[k].x, 16);
            acc[k].y += __shfl_xor_sync(0xffffffffu, acc[k].y, 16);
            acc[k].z += __shfl_xor_sync(0xffffffffu, acc[k].z, 16);
            acc[k].w += __shfl_xor_sync(0xffffffffu, acc[k].w, 16);
        }
        if (lane < 8) {
            float4* op = reinterpret_cast<float4*>(out + (size_t)w * COUT);
            const float4* bp = reinterpret_cast<const float4*>(bias);
#pragma unroll
            for (int k = 0; k < 4; k++) {
                float4 b4 = bp[lane * 4 + k];
                float4 v = acc[k];
                v.x = 0.25f * v.x + b4.x; v.y = 0.25f * v.y + b4.y;
                v.z = 0.25f * v.z + b4.z; v.w = 0.25f * v.w + b4.w;
                op[lane * 4 + k] = v;
            }
        }
    }
}

// ---------------- host ----------------
extern "C" void kernel_launch(void* const* d_in, const int* in_sizes, int n_in,
                              void* d_out, int out_size)
{
    const float* x      = (const float*)d_in[0];
    const int*   ei     = (const int*)d_in[1];
    const float* W1     = (const float*)d_in[2];
    const float* a_src1 = (const float*)d_in[3];
    const float* a_dst1 = (const float*)d_in[4];
    const float* b1     = (const float*)d_in[5];
    const float* W2     = (const float*)d_in[6];
    const float* a_src2 = (const float*)d_in[7];
    const float* a_dst2 = (const float*)d_in[8];
    const float* b2     = (const float*)d_in[9];

    const int N = in_sizes[0] / CIN;
    const int E = in_sizes[1] / 2;

    void *p_hf1, *p_hf2, *p_agg1, *p_as1, *p_ad1, *p_as2, *p_ad2, *p_cnt;
    cudaGetSymbolAddress(&p_hf1, g_hf1);
    cudaGetSymbolAddress(&p_hf2, g_hf2);
    cudaGetSymbolAddress(&p_agg1, g_agg1);
    cudaGetSymbolAddress(&p_as1, g_as1);
    cudaGetSymbolAddress(&p_ad1, g_ad1);
    cudaGetSymbolAddress(&p_as2, g_as2);
    cudaGetSymbolAddress(&p_ad2, g_ad2);
    cudaGetSymbolAddress(&p_cnt, g_counts);
    __half* hf1 = (__half*)p_hf1;
    __half* hf2 = (__half*)p_hf2;
    float* agg1 = (float*)p_agg1;
    float* as1  = (float*)p_as1;
    float* ad1  = (float*)p_ad1;
    float* as2  = (float*)p_as2;
    float* ad2  = (float*)p_ad2;
    float* out  = (float*)d_out;

    // CSR build (deterministic work every call)
    cudaMemsetAsync(p_cnt, 0, (size_t)N * sizeof(int));
    k_count<<<(E + 255) / 256, 256>>>(ei, E);
    k_scan<<<1, 1024>>>(N);
    k_scatter<<<(E + N + 255) / 256, 256>>>(ei, E, N);

    const int warpsGrid = (N * 32 + 255) / 256;
    const dim3 gg(HH, (N + 127) / 128);   // 4 heads x 79 row tiles

    // layer 1: fused GEMM + attn dots, then aggregate (+b1)
    k_gemm_attn<false><<<gg, 256>>>(x, W1, hf1, as1, ad1, a_src1, a_dst1, N, CIN);
    k_agg<false><<<warpsGrid, 256>>>(hf1, as1, ad1, b1, agg1, N);

    // layer 2: ReLU fused into GEMM2's A-side split; head-mean + b2 in agg
    k_gemm_attn<true><<<gg, 256>>>(agg1, W2, hf2, as2, ad2, a_src2, a_dst2, N, FF);
    k_agg<true><<<warpsGrid, 256>>>(hf2, as2, ad2, b2, out, N);
}

// round 15
// speedup vs baseline: 2.0336x; 1.0622x over previous
#include <cuda_runtime.h>
#include <cuda_fp16.h>
#include <cstdint>

// Problem constants (fixed by the dataset)
#define NN   10000
#define EE   320000
#define HH   4
#define CIN  256
#define FF   512          // H*HID = H*OUT = per-node feature width in both layers
#define COUT 128
#define SLOPE 0.2f

// ---------------- scratch (static device globals; no allocation) ----------------
__device__ __half g_hf1[NN * FF];       // layer-1 features (fp16, gather source)
__device__ __half g_hf2[NN * FF];       // layer-2 features
__device__ __half g_xs_hi[NN * CIN];    // x pre-split
__device__ __half g_xs_lo[NN * CIN];
__device__ __half g_a2_hi[NN * FF];     // relu(layer1 out) pre-split (written by k_agg)
__device__ __half g_a2_lo[NN * FF];
__device__ __half g_w1_hi[FF * CIN];    // W1^T [512][256] split
__device__ __half g_w1_lo[FF * CIN];
__device__ __half g_w2_hi[FF * FF];     // W2^T [512][512] split
__device__ __half g_w2_lo[FF * FF];
__device__ float g_as1[NN * HH];
__device__ float g_ad1[NN * HH];
__device__ float g_as2[NN * HH];
__device__ float g_ad2[NN * HH];
__device__ int   g_counts[NN];
__device__ int   g_rowptr[NN + 1];
__device__ int   g_cursor[NN];
__device__ int   g_srcsorted[EE + NN];

// ---------------- CSR build ----------------
__global__ void k_count(const int* __restrict__ ei, int E) {
    int i = blockIdx.x * blockDim.x + threadIdx.x;
    if (i < E) atomicAdd(&g_counts[ei[E + i]], 1);
}

// single-block exclusive scan of (g_counts[i]+1) -> g_rowptr, g_cursor
__global__ void k_scan(int n) {
    __shared__ int sb[1024];
    int tid = threadIdx.x;
    int per = (n + 1023) >> 10;
    int base = tid * per;
    int sum = 0;
    for (int i = 0; i < per; i++) {
        int idx = base + i;
        if (idx < n) sum += g_counts[idx] + 1;
    }
    sb[tid] = sum;
    __syncthreads();
    for (int off = 1; off < 1024; off <<= 1) {
        int v = (tid >= off) ? sb[tid - off] : 0;
        __syncthreads();
        sb[tid] += v;
        __syncthreads();
    }
    int run = sb[tid] - sum;
    for (int i = 0; i < per; i++) {
        int idx = base + i;
        if (idx < n) {
            g_rowptr[idx] = run;
            g_cursor[idx] = run;
            run += g_counts[idx] + 1;
        }
    }
    if (tid == 1023) g_rowptr[n] = sb[1023];
}

__global__ void k_scatter(const int* __restrict__ ei, int E, int n) {
    int i = blockIdx.x * blockDim.x + threadIdx.x;
    int total = E + n;
    if (i >= total) return;
    int s, d;
    if (i < E) { s = ei[i]; d = ei[E + i]; }
    else       { s = i - E; d = s; }
    int pos = atomicAdd(&g_cursor[d], 1);
    g_srcsorted[pos] = s;
}

// ---------------- fp16 split helpers ----------------
__device__ __forceinline__ void f16split(float v, __half& hi, __half& lo) {
    hi = __float2half_rn(v);
    lo = __float2half_rn(v - __half2float(hi));
}

__device__ __forceinline__ void mma_f16(float* d, const uint32_t* a, const uint32_t* b) {
    asm volatile(
        "mma.sync.aligned.m16n8k16.row.col.f32.f16.f16.f32 "
        "{%0,%1,%2,%3}, {%4,%5,%6,%7}, {%8,%9}, {%0,%1,%2,%3};"
        : "+f"(d[0]), "+f"(d[1]), "+f"(d[2]), "+f"(d[3])
        : "r"(a[0]), "r"(a[1]), "r"(a[2]), "r"(a[3]), "r"(b[0]), "r"(b[1]));
}

__device__ __forceinline__ uint32_t smem_u32(const void* p) {
    uint32_t a;
    asm("{ .reg .u64 t; cvta.to.shared.u64 t, %1; cvt.u32.u64 %0, t; }" : "=r"(a) : "l"(p));
    return a;
}

#define LDSM_X4(r, addr) \
    asm volatile("ldmatrix.sync.aligned.m8n8.x4.shared.b16 {%0,%1,%2,%3}, [%4];" \
        : "=r"((r)[0]), "=r"((r)[1]), "=r"((r)[2]), "=r"((r)[3]) : "r"(addr))
#define LDSM_X2(r0, r1, addr) \
    asm volatile("ldmatrix.sync.aligned.m8n8.x2.shared.b16 {%0,%1}, [%2];" \
        : "=r"(r0), "=r"(r1) : "r"(addr))

// ---------------- pre-split kernels ----------------
// W [K][512] -> hi/lo [512][K]  (transpose + split)
__global__ void k_splitW(const float* __restrict__ W, __half* __restrict__ whi,
                         __half* __restrict__ wlo, int K)
{
    __shared__ float t[32][33];
    int n0 = blockIdx.x * 32, k0 = blockIdx.y * 32;
    int tx = threadIdx.x, ty = threadIdx.y;
#pragma unroll
    for (int i = 0; i < 32; i += 8)
        t[ty + i][tx] = W[(size_t)(k0 + ty + i) * FF + n0 + tx];
    __syncthreads();
#pragma unroll
    for (int i = 0; i < 32; i += 8) {
        float v = t[tx][ty + i];
        __half h, l;
        f16split(v, h, l);
        size_t o = (size_t)(n0 + ty + i) * K + k0 + tx;
        whi[o] = h;
        wlo[o] = l;
    }
}

// x [N][CIN] -> hi/lo halves (elementwise, 8 per thread)
__global__ void k_splitX(const float* __restrict__ x, __half* __restrict__ xhi,
                         __half* __restrict__ xlo, int total8)
{
    int i = blockIdx.x * blockDim.x + threadIdx.x;
    if (i >= total8) return;
    const float4* xp = reinterpret_cast<const float4*>(x) + (size_t)i * 2;
    float4 v0 = xp[0], v1 = xp[1];
    float v[8] = {v0.x, v0.y, v0.z, v0.w, v1.x, v1.y, v1.z, v1.w};
    __half h[8], l[8];
#pragma unroll
    for (int j = 0; j < 8; j++) f16split(v[j], h[j], l[j]);
    uint32_t ph[4], pl[4];
#pragma unroll
    for (int j = 0; j < 4; j++) {
        __half2 a = __halves2half2(h[2 * j], h[2 * j + 1]);
        __half2 b = __halves2half2(l[2 * j], l[2 * j + 1]);
        ph[j] = *reinterpret_cast<uint32_t*>(&a);
        pl[j] = *reinterpret_cast<uint32_t*>(&b);
    }
    reinterpret_cast<uint4*>(xhi)[i] = make_uint4(ph[0], ph[1], ph[2], ph[3]);
    reinterpret_cast<uint4*>(xlo)[i] = make_uint4(pl[0], pl[1], pl[2], pl[3]);
}

// ---------------- fused GEMM + attention-coefficient kernel ----------------
// C = A @ W (A,W pre-split fp16 hi/lo; 3-term compensated mma, fp32 accum).
// CTA: 128 rows x one head (128 cols). 8 warps 2x4; warp tile 64x32.
// SMEM rows padded to 24 halves (48B) -> conflict-free STS.128 phases and LDSM.
#define RSTRIDE 24                 // halves per smem row
#define REGION  (128 * RSTRIDE)    // halves per [stage][split] region (3072)
#define REGB    (REGION * 2)       // bytes per region (6144)

__global__ __launch_bounds__(256, 2)
void k_gemm(const __half* __restrict__ Ahi, const __half* __restrict__ Alo,
            const __half* __restrict__ Bhi, const __half* __restrict__ Blo,
            __half* __restrict__ hf, float* __restrict__ as, float* __restrict__ ad,
            const float* __restrict__ a_src, const float* __restrict__ a_dst,
            int M, int K)
{
    __shared__ __align__(16) __half sm[2][2][2][REGION];  // [A/B][stage][split]

    const int tid  = threadIdx.x;
    const int wid  = tid >> 5;
    const int lane = tid & 31;
    const int g    = lane >> 2;
    const int tg   = lane & 3;
    const int wm   = wid >> 2;
    const int wn   = wid & 3;
    const int mb   = wm * 64;
    const int nb   = wn * 32;

    const int head = blockIdx.x;
    const int brow = blockIdx.y * 128;

    // staging: thread owns one full 16-half row-chunk of A and of B, one split
    const int rsel  = tid & 127;
    const int split = tid >> 7;
    const int row   = brow + rsel;
    const bool okA  = row < M;
    const __half* Ap = (split ? Alo : Ahi) + (size_t)row * K;
    const __half* Bp = (split ? Blo : Bhi) + (size_t)(head * 128 + rsel) * K;

    float acc[4][4][4];
#pragma unroll
    for (int mt = 0; mt < 4; mt++)
#pragma unroll
        for (int nt = 0; nt < 4; nt++)
#pragma unroll
            for (int q = 0; q < 4; q++) acc[mt][nt][q] = 0.f;

    const uint32_t smbase = smem_u32(&sm[0][0][0][0]);
    // per-lane ldmatrix byte offsets
    const uint32_t aoff = (uint32_t)((mb + (lane & 7) + (lane & 8)) * 48 + ((lane & 16) ? 16 : 0));
    const int bl = lane & 15;
    const uint32_t boff = (uint32_t)((nb + (bl & 7)) * 48 + ((bl & 8) ? 16 : 0));

    // preload first chunk
    uint4 qa0 = make_uint4(0, 0, 0, 0), qa1 = qa0, qb0, qb1;
    if (okA) {
        qa0 = *reinterpret_cast<const uint4*>(Ap);
        qa1 = *reinterpret_cast<const uint4*>(Ap + 8);
    }
    qb0 = *reinterpret_cast<const uint4*>(Bp);
    qb1 = *reinterpret_cast<const uint4*>(Bp + 8);

    const int nk = K >> 4;
    for (int t = 0; t < nk; t++) {
        const int cur = t & 1;
        {
            __half* da = &sm[0][cur][split][rsel * RSTRIDE];
            *reinterpret_cast<uint4*>(da)     = qa0;
            *reinterpret_cast<uint4*>(da + 8) = qa1;
            __half* db = &sm[1][cur][split][rsel * RSTRIDE];
            *reinterpret_cast<uint4*>(db)     = qb0;
            *reinterpret_cast<uint4*>(db + 8) = qb1;
        }
        __syncthreads();

        if (t + 1 < nk) {
            const int k0 = (t + 1) * 16;
            if (okA) {
                qa0 = *reinterpret_cast<const uint4*>(Ap + k0);
                qa1 = *reinterpret_cast<const uint4*>(Ap + k0 + 8);
            }
            qb0 = *reinterpret_cast<const uint4*>(Bp + k0);
            qb1 = *reinterpret_cast<const uint4*>(Bp + k0 + 8);
        }

        const uint32_t Ah = smbase + (cur * 2 + 0) * REGB + aoff;
        const uint32_t Al = smbase + (cur * 2 + 1) * REGB + aoff;
        const uint32_t Bh = smbase + 4 * REGB + (cur * 2 + 0) * REGB + boff;
        const uint32_t Bl = smbase + 4 * REGB + (cur * 2 + 1) * REGB + boff;

        uint32_t bh[4][2], blo[4][2];
#pragma unroll
        for (int nt = 0; nt < 4; nt++) {
            LDSM_X2(bh[nt][0],  bh[nt][1],  Bh + nt * 384);
            LDSM_X2(blo[nt][0], blo[nt][1], Bl + nt * 384);
        }
#pragma unroll
        for (int mt = 0; mt < 4; mt++) {
            uint32_t ah[4], al[4];
            LDSM_X4(ah, Ah + mt * 768);
            LDSM_X4(al, Al + mt * 768);
#pragma unroll
            for (int nt = 0; nt < 4; nt++) {
                mma_f16(acc[mt][nt], ah, bh[nt]);    // hi*hi
                mma_f16(acc[mt][nt], al, bh[nt]);    // lo*hi
                mma_f16(acc[mt][nt], ah, blo[nt]);   // hi*lo
            }
        }
        __syncthreads();
    }

    // ---- epilogue: fp16 store + fused attention dots ----
    float* sred = reinterpret_cast<float*>(&sm[0][0][0][0]);  // overlay, [2][128][4]

    float asv0[4], asv1[4], adv0[4], adv1[4];
#pragma unroll
    for (int nt = 0; nt < 4; nt++) {
        int c = nb + nt * 8 + 2 * tg;
        asv0[nt] = a_src[head * 128 + c];
        asv1[nt] = a_src[head * 128 + c + 1];
        adv0[nt] = a_dst[head * 128 + c];
        adv1[nt] = a_dst[head * 128 + c + 1];
    }

#pragma unroll
    for (int mt = 0; mt < 4; mt++) {
#pragma unroll
        for (int rh = 0; rh < 2; rh++) {
            int rloc = mb + mt * 16 + rh * 8 + g;
            int r    = brow + rloc;
            float ps = 0.f, pd = 0.f;
#pragma unroll
            for (int nt = 0; nt < 4; nt++) {
                float c0 = acc[mt][nt][rh * 2];
                float c1 = acc[mt][nt][rh * 2 + 1];
                ps = fmaf(c0, asv0[nt], fmaf(c1, asv1[nt], ps));
                pd = fmaf(c0, adv0[nt], fmaf(c1, adv1[nt], pd));
                if (r < M) {
                    int col = head * 128 + nb + nt * 8 + 2 * tg;
                    *reinterpret_cast<__half2*>(hf + (size_t)r * FF + col) =
                        __floats2half2_rn(c0, c1);
                }
            }
            ps += __shfl_xor_sync(0xffffffffu, ps, 1);
            ps += __shfl_xor_sync(0xffffffffu, ps, 2);
            pd += __shfl_xor_sync(0xffffffffu, pd, 1);
            pd += __shfl_xor_sync(0xffffffffu, pd, 2);
            if (tg == 0) {
                sred[(0 * 128 + rloc) * 4 + wn] = ps;
                sred[(1 * 128 + rloc) * 4 + wn] = pd;
            }
        }
    }
    __syncthreads();
    if (tid < 128) {
        int r = brow + tid;
        if (r < M) {
            float s = sred[tid * 4] + sred[tid * 4 + 1] + sred[tid * 4 + 2] + sred[tid * 4 + 3];
            float d = sred[(128 + tid) * 4] + sred[(128 + tid) * 4 + 1]
                    + sred[(128 + tid) * 4 + 2] + sred[(128 + tid) * 4 + 3];
            as[r * HH + head] = s;
            ad[r * HH + head] = d;
        }
    }
}

__device__ __forceinline__ float lrelu(float z) { return z > 0.f ? z : SLOPE * z; }
__device__ __forceinline__ float sel4(float4 a, int h) {
    float v = a.x;
    if (h == 1) v = a.y;
    if (h == 2) v = a.z;
    if (h == 3) v = a.w;
    return v;
}

// ---------------- per-dst aggregation with segment softmax ----------------
// one warp per dst node; 3 passes. MEAN=false: emit relu'd split halves (layer-2 A).
// MEAN=true: head-mean + bias, fp32 out (final output).
template <bool MEAN>
__global__ __launch_bounds__(256)
void k_agg(const __half* __restrict__ hfeat, const float* __restrict__ as,
           const float* __restrict__ ad, const float* __restrict__ bias,
           float* __restrict__ out, __half* __restrict__ ohi, __half* __restrict__ olo,
           int n)
{
    int w = (blockIdx.x * blockDim.x + threadIdx.x) >> 5;
    if (w >= n) return;
    int lane = threadIdx.x & 31;
    int start = g_rowptr[w], end = g_rowptr[w + 1];

    float4 adv = *reinterpret_cast<const float4*>(ad + (size_t)w * 4);

    // pass 1: per-head max
    float m0 = -3.4e38f, m1 = -3.4e38f, m2 = -3.4e38f, m3 = -3.4e38f;
    for (int j = start + lane; j < end; j += 32) {
        int s = g_srcsorted[j];
        float4 a = *reinterpret_cast<const float4*>(as + (size_t)s * 4);
        m0 = fmaxf(m0, lrelu(a.x + adv.x));
        m1 = fmaxf(m1, lrelu(a.y + adv.y));
        m2 = fmaxf(m2, lrelu(a.z + adv.z));
        m3 = fmaxf(m3, lrelu(a.w + adv.w));
    }
#pragma unroll
    for (int off = 16; off; off >>= 1) {
        m0 = fmaxf(m0, __shfl_xor_sync(0xffffffffu, m0, off));
        m1 = fmaxf(m1, __shfl_xor_sync(0xffffffffu, m1, off));
        m2 = fmaxf(m2, __shfl_xor_sync(0xffffffffu, m2, off));
        m3 = fmaxf(m3, __shfl_xor_sync(0xffffffffu, m3, off));
    }

    // pass 2: per-head sum of exp
    float d0 = 0.f, d1 = 0.f, d2 = 0.f, d3 = 0.f;
    for (int j = start + lane; j < end; j += 32) {
        int s = g_srcsorted[j];
        float4 a = *reinterpret_cast<const float4*>(as + (size_t)s * 4);
        d0 += __expf(lrelu(a.x + adv.x) - m0);
        d1 += __expf(lrelu(a.y + adv.y) - m1);
        d2 += __expf(lrelu(a.z + adv.z) - m2);
        d3 += __expf(lrelu(a.w + adv.w) - m3);
    }
#pragma unroll
    for (int off = 16; off; off >>= 1) {
        d0 += __shfl_xor_sync(0xffffffffu, d0, off);
        d1 += __shfl_xor_sync(0xffffffffu, d1, off);
        d2 += __shfl_xor_sync(0xffffffffu, d2, off);
        d3 += __shfl_xor_sync(0xffffffffu, d3, off);
    }
    float i0 = 1.f / (d0 + 1e-16f);
    float i1 = 1.f / (d1 + 1e-16f);
    float i2 = 1.f / (d2 + 1e-16f);
    float i3 = 1.f / (d3 + 1e-16f);

    // pass 3: weighted fp16 feature gather; lane owns 16 contiguous channels
    const int hsel = lane >> 3;
    const float mm = sel4(make_float4(m0, m1, m2, m3), hsel);
    const float ii = sel4(make_float4(i0, i1, i2, i3), hsel);
    const float aD = sel4(adv, hsel);

    float4 acc[4];
#pragma unroll
    for (int k = 0; k < 4; k++) acc[k] = make_float4(0.f, 0.f, 0.f, 0.f);

    for (int j = start; j < end; j++) {
        int s = g_srcsorted[j];
        float4 a = *reinterpret_cast<const float4*>(as + (size_t)s * 4);
        float wgt = __expf(lrelu(sel4(a, hsel) + aD) - mm) * ii;
        const uint4* hp = reinterpret_cast<const uint4*>(hfeat + (size_t)s * FF) + lane * 2;
        uint4 q0 = hp[0];
        uint4 q1 = hp[1];
        const __half2* ph = reinterpret_cast<const __half2*>(&q0);
#pragma unroll
        for (int k = 0; k < 2; k++) {
            float2 fa = __half22float2(ph[2 * k]);
            float2 fb = __half22float2(ph[2 * k + 1]);
            acc[k].x = fmaf(wgt, fa.x, acc[k].x);
            acc[k].y = fmaf(wgt, fa.y, acc[k].y);
            acc[k].z = fmaf(wgt, fb.x, acc[k].z);
            acc[k].w = fmaf(wgt, fb.y, acc[k].w);
        }
        const __half2* qh = reinterpret_cast<const __half2*>(&q1);
#pragma unroll
        for (int k = 0; k < 2; k++) {
            float2 fa = __half22float2(qh[2 * k]);
            float2 fb = __half22float2(qh[2 * k + 1]);
            acc[k + 2].x = fmaf(wgt, fa.x, acc[k + 2].x);
            acc[k + 2].y = fmaf(wgt, fa.y, acc[k + 2].y);
            acc[k + 2].z = fmaf(wgt, fb.x, acc[k + 2].z);
            acc[k + 2].w = fmaf(wgt, fb.y, acc[k + 2].w);
        }
    }

    if (!MEAN) {
        // bias + relu + fp16-split write (this IS layer-2's A operand)
        __half2* oh = reinterpret_cast<__half2*>(ohi + (size_t)w * FF + lane * 16);
        __half2* ol = reinterpret_cast<__half2*>(olo + (size_t)w * FF + lane * 16);
        const float4* bp = reinterpret_cast<const float4*>(bias);
#pragma unroll
        for (int k = 0; k < 4; k++) {
            float4 b4 = bp[lane * 4 + k];
            float4 v = acc[k];
            v.x = fmaxf(v.x + b4.x, 0.f);
            v.y = fmaxf(v.y + b4.y, 0.f);
            v.z = fmaxf(v.z + b4.z, 0.f);
            v.w = fmaxf(v.w + b4.w, 0.f);
            __half hx, lx, hy, ly, hz, lz, hw, lw;
            f16split(v.x, hx, lx); f16split(v.y, hy, ly);
            f16split(v.z, hz, lz); f16split(v.w, hw, lw);
            oh[2 * k]     = __halves2half2(hx, hy);
            oh[2 * k + 1] = __halves2half2(hz, hw);
            ol[2 * k]     = __halves2half2(lx, ly);
            ol[2 * k + 1] = __halves2half2(lz, lw);
        }
    } else {
        // mean over heads: sum lanes {l, l^8, l^16, l^24}, lanes 0..7 write 128 channels
#pragma unroll
        for (int k = 0; k < 4; k++) {
            acc[k].x += __shfl_xor_sync(0xffffffffu, acc[k].x, 8);
            acc[k].y += __shfl_xor_sync(0xffffffffu, acc[k].y, 8);
            acc[k].z += __shfl_xor_sync(0xffffffffu, acc[k].z, 8);
            acc[k].w += __shfl_xor_sync(0xffffffffu, acc[k].w, 8);
            acc[k].x += __shfl_xor_sync(0xffffffffu, acc[k].x, 16);
            acc[k].y += __shfl_xor_sync(0xffffffffu, acc[k].y, 16);
            acc[k].z += __shfl_xor_sync(0xffffffffu, acc[k].z, 16);
            acc[k].w += __shfl_xor_sync(0xffffffffu, acc[k].w, 16);
        }
        if (lane < 8) {
            float4* op = reinterpret_cast<float4*>(out + (size_t)w * COUT);
            const float4* bp = reinterpret_cast<const float4*>(bias);
#pragma unroll
            for (int k = 0; k < 4; k++) {
                float4 b4 = bp[lane * 4 + k];
                float4 v = acc[k];
                v.x = 0.25f * v.x + b4.x; v.y = 0.25f * v.y + b4.y;
                v.z = 0.25f * v.z + b4.z; v.w = 0.25f * v.w + b4.w;
                op[lane * 4 + k] = v;
            }
        }
    }
}

// ---------------- host ----------------
extern "C" void kernel_launch(void* const* d_in, const int* in_sizes, int n_in,
                              void* d_out, int out_size)
{
    const float* x      = (const float*)d_in[0];
    const int*   ei     = (const int*)d_in[1];
    const float* W1     = (const float*)d_in[2];
    const float* a_src1 = (const float*)d_in[3];
    const float* a_dst1 = (const float*)d_in[4];
    const float* b1     = (const float*)d_in[5];
    const float* W2     = (const float*)d_in[6];
    const float* a_src2 = (const float*)d_in[7];
    const float* a_dst2 = (const float*)d_in[8];
    const float* b2     = (const float*)d_in[9];

    const int N = in_sizes[0] / CIN;
    const int E = in_sizes[1] / 2;

    void *p_hf1, *p_hf2, *p_xh, *p_xl, *p_ah, *p_al, *p_w1h, *p_w1l, *p_w2h, *p_w2l;
    void *p_as1, *p_ad1, *p_as2, *p_ad2, *p_cnt;
    cudaGetSymbolAddress(&p_hf1, g_hf1);
    cudaGetSymbolAddress(&p_hf2, g_hf2);
    cudaGetSymbolAddress(&p_xh, g_xs_hi);
    cudaGetSymbolAddress(&p_xl, g_xs_lo);
    cudaGetSymbolAddress(&p_ah, g_a2_hi);
    cudaGetSymbolAddress(&p_al, g_a2_lo);
    cudaGetSymbolAddress(&p_w1h, g_w1_hi);
    cudaGetSymbolAddress(&p_w1l, g_w1_lo);
    cudaGetSymbolAddress(&p_w2h, g_w2_hi);
    cudaGetSymbolAddress(&p_w2l, g_w2_lo);
    cudaGetSymbolAddress(&p_as1, g_as1);
    cudaGetSymbolAddress(&p_ad1, g_ad1);
    cudaGetSymbolAddress(&p_as2, g_as2);
    cudaGetSymbolAddress(&p_ad2, g_ad2);
    cudaGetSymbolAddress(&p_cnt, g_counts);
    __half* hf1 = (__half*)p_hf1;
    __half* hf2 = (__half*)p_hf2;
    float* as1 = (float*)p_as1;
    float* ad1 = (float*)p_ad1;
    float* as2 = (float*)p_as2;
    float* ad2 = (float*)p_ad2;
    float* out = (float*)d_out;

    // CSR build
    cudaMemsetAsync(p_cnt, 0, (size_t)N * sizeof(int));
    k_count<<<(E + 255) / 256, 256>>>(ei, E);
    k_scan<<<1, 1024>>>(N);
    k_scatter<<<(E + N + 255) / 256, 256>>>(ei, E, N);

    // pre-split operands
    k_splitW<<<dim3(FF / 32, CIN / 32), dim3(32, 8)>>>(W1, (__half*)p_w1h, (__half*)p_w1l, CIN);
    k_splitW<<<dim3(FF / 32, FF / 32),  dim3(32, 8)>>>(W2, (__half*)p_w2h, (__half*)p_w2l, FF);
    const int tot8 = N * CIN / 8;
    k_splitX<<<(tot8 + 255) / 256, 256>>>(x, (__half*)p_xh, (__half*)p_xl, tot8);

    const int warpsGrid = (N * 32 + 255) / 256;
    const dim3 gg(HH, (N + 127) / 128);

    // layer 1
    k_gemm<<<gg, 256>>>((__half*)p_xh, (__half*)p_xl, (__half*)p_w1h, (__half*)p_w1l,
                        hf1, as1, ad1, a_src1, a_dst1, N, CIN);
    k_agg<false><<<warpsGrid, 256>>>(hf1, as1, ad1, b1, nullptr,
                                     (__half*)p_ah, (__half*)p_al, N);

    // layer 2 (A = relu'd split halves from k_agg)
    k_gemm<<<gg, 256>>>((__half*)p_ah, (__half*)p_al, (__half*)p_w2h, (__half*)p_w2l,
                        hf2, as2, ad2, a_src2, a_dst2, N, FF);
    k_agg<true><<<warpsGrid, 256>>>(hf2, as2, ad2, b2, out, nullptr, nullptr, N);
}

// round 16
// speedup vs baseline: 2.1098x; 1.0374x over previous
#include <cuda_runtime.h>
#include <cuda_fp16.h>
#include <cstdint>

// Problem constants (fixed by the dataset)
#define NN   10000
#define EE   320000
#define HH   4
#define CIN  256
#define FF   512          // H*HID = H*OUT = per-node feature width in both layers
#define COUT 128
#define SLOPE 0.2f

// ---------------- scratch (static device globals; no allocation) ----------------
__device__ __half g_hf1[NN * FF];       // layer-1 features (fp16, gather source)
__device__ __half g_hf2[NN * FF];       // layer-2 features
__device__ __half g_xs_hi[NN * CIN];    // x pre-split
__device__ __half g_xs_lo[NN * CIN];
__device__ __half g_a2_hi[NN * FF];     // relu(layer1 out) pre-split (written by k_agg)
__device__ __half g_a2_lo[NN * FF];
__device__ __half g_w1_hi[FF * CIN];    // W1^T [512][256] split
__device__ __half g_w1_lo[FF * CIN];
__device__ __half g_w2_hi[FF * FF];     // W2^T [512][512] split
__device__ __half g_w2_lo[FF * FF];
__device__ float g_as1[NN * HH];
__device__ float g_ad1[NN * HH];
__device__ float g_as2[NN * HH];
__device__ float g_ad2[NN * HH];
__device__ float g_wgt[(EE + NN) * HH]; // per-edge unnormalized softmax weights (4 heads)
__device__ int   g_counts[NN];
__device__ int   g_rowptr[NN + 1];
__device__ int   g_cursor[NN];
__device__ int   g_srcsorted[EE + NN];

// ---------------- CSR build ----------------
__global__ void k_count(const int* __restrict__ ei, int E) {
    int i = blockIdx.x * blockDim.x + threadIdx.x;
    if (i < E) atomicAdd(&g_counts[ei[E + i]], 1);
}

// single-block exclusive scan of (g_counts[i]+1) -> g_rowptr, g_cursor
__global__ void k_scan(int n) {
    __shared__ int sb[1024];
    int tid = threadIdx.x;
    int per = (n + 1023) >> 10;
    int base = tid * per;
    int sum = 0;
    for (int i = 0; i < per; i++) {
        int idx = base + i;
        if (idx < n) sum += g_counts[idx] + 1;
    }
    sb[tid] = sum;
    __syncthreads();
    for (int off = 1; off < 1024; off <<= 1) {
        int v = (tid >= off) ? sb[tid - off] : 0;
        __syncthreads();
        sb[tid] += v;
        __syncthreads();
    }
    int run = sb[tid] - sum;
    for (int i = 0; i < per; i++) {
        int idx = base + i;
        if (idx < n) {
            g_rowptr[idx] = run;
            g_cursor[idx] = run;
            run += g_counts[idx] + 1;
        }
    }
    if (tid == 1023) g_rowptr[n] = sb[1023];
}

__global__ void k_scatter(const int* __restrict__ ei, int E, int n) {
    int i = blockIdx.x * blockDim.x + threadIdx.x;
    int total = E + n;
    if (i >= total) return;
    int s, d;
    if (i < E) { s = ei[i]; d = ei[E + i]; }
    else       { s = i - E; d = s; }
    int pos = atomicAdd(&g_cursor[d], 1);
    g_srcsorted[pos] = s;
}

// ---------------- fp16 split helpers ----------------
__device__ __forceinline__ void f16split(float v, __half& hi, __half& lo) {
    hi = __float2half_rn(v);
    lo = __float2half_rn(v - __half2float(hi));
}

__device__ __forceinline__ void mma_f16(float* d, const uint32_t* a, const uint32_t* b) {
    asm volatile(
        "mma.sync.aligned.m16n8k16.row.col.f32.f16.f16.f32 "
        "{%0,%1,%2,%3}, {%4,%5,%6,%7}, {%8,%9}, {%0,%1,%2,%3};"
        : "+f"(d[0]), "+f"(d[1]), "+f"(d[2]), "+f"(d[3])
        : "r"(a[0]), "r"(a[1]), "r"(a[2]), "r"(a[3]), "r"(b[0]), "r"(b[1]));
}

__device__ __forceinline__ uint32_t smem_u32(const void* p) {
    uint32_t a;
    asm("{ .reg .u64 t; cvta.to.shared.u64 t, %1; cvt.u32.u64 %0, t; }" : "=r"(a) : "l"(p));
    return a;
}

#define LDSM_X4(r, addr) \
    asm volatile("ldmatrix.sync.aligned.m8n8.x4.shared.b16 {%0,%1,%2,%3}, [%4];" \
        : "=r"((r)[0]), "=r"((r)[1]), "=r"((r)[2]), "=r"((r)[3]) : "r"(addr))
#define LDSM_X2(r0, r1, addr) \
    asm volatile("ldmatrix.sync.aligned.m8n8.x2.shared.b16 {%0,%1}, [%2];" \
        : "=r"(r0), "=r"(r1) : "r"(addr))

// ---------------- pre-split kernels ----------------
// W [K][512] -> hi/lo [512][K]  (transpose + split)
__global__ void k_splitW(const float* __restrict__ W, __half* __restrict__ whi,
                         __half* __restrict__ wlo, int K)
{
    __shared__ float t[32][33];
    int n0 = blockIdx.x * 32, k0 = blockIdx.y * 32;
    int tx = threadIdx.x, ty = threadIdx.y;
#pragma unroll
    for (int i = 0; i < 32; i += 8)
        t[ty + i][tx] = W[(size_t)(k0 + ty + i) * FF + n0 + tx];
    __syncthreads();
#pragma unroll
    for (int i = 0; i < 32; i += 8) {
        float v = t[tx][ty + i];
        __half h, l;
        f16split(v, h, l);
        size_t o = (size_t)(n0 + ty + i) * K + k0 + tx;
        whi[o] = h;
        wlo[o] = l;
    }
}

// x [N][CIN] -> hi/lo halves (elementwise, 8 per thread)
__global__ void k_splitX(const float* __restrict__ x, __half* __restrict__ xhi,
                         __half* __restrict__ xlo, int total8)
{
    int i = blockIdx.x * blockDim.x + threadIdx.x;
    if (i >= total8) return;
    const float4* xp = reinterpret_cast<const float4*>(x) + (size_t)i * 2;
    float4 v0 = xp[0], v1 = xp[1];
    float v[8] = {v0.x, v0.y, v0.z, v0.w, v1.x, v1.y, v1.z, v1.w};
    __half h[8], l[8];
#pragma unroll
    for (int j = 0; j < 8; j++) f16split(v[j], h[j], l[j]);
    uint32_t ph[4], pl[4];
#pragma unroll
    for (int j = 0; j < 4; j++) {
        __half2 a = __halves2half2(h[2 * j], h[2 * j + 1]);
        __half2 b = __halves2half2(l[2 * j], l[2 * j + 1]);
        ph[j] = *reinterpret_cast<uint32_t*>(&a);
        pl[j] = *reinterpret_cast<uint32_t*>(&b);
    }
    reinterpret_cast<uint4*>(xhi)[i] = make_uint4(ph[0], ph[1], ph[2], ph[3]);
    reinterpret_cast<uint4*>(xlo)[i] = make_uint4(pl[0], pl[1], pl[2], pl[3]);
}

// ---------------- fused GEMM + attention-coefficient kernel ----------------
#define RSTRIDE 24                 // halves per smem row
#define REGION  (128 * RSTRIDE)    // halves per [stage][split] region (3072)
#define REGB    (REGION * 2)       // bytes per region (6144)

__global__ __launch_bounds__(256, 2)
void k_gemm(const __half* __restrict__ Ahi, const __half* __restrict__ Alo,
            const __half* __restrict__ Bhi, const __half* __restrict__ Blo,
            __half* __restrict__ hf, float* __restrict__ as, float* __restrict__ ad,
            const float* __restrict__ a_src, const float* __restrict__ a_dst,
            int M, int K)
{
    __shared__ __align__(16) __half sm[2][2][2][REGION];  // [A/B][stage][split]

    const int tid  = threadIdx.x;
    const int wid  = tid >> 5;
    const int lane = tid & 31;
    const int g    = lane >> 2;
    const int tg   = lane & 3;
    const int wm   = wid >> 2;
    const int wn   = wid & 3;
    const int mb   = wm * 64;
    const int nb   = wn * 32;

    const int head = blockIdx.x;
    const int brow = blockIdx.y * 128;

    const int rsel  = tid & 127;
    const int split = tid >> 7;
    const int row   = brow + rsel;
    const bool okA  = row < M;
    const __half* Ap = (split ? Alo : Ahi) + (size_t)row * K;
    const __half* Bp = (split ? Blo : Bhi) + (size_t)(head * 128 + rsel) * K;

    float acc[4][4][4];
#pragma unroll
    for (int mt = 0; mt < 4; mt++)
#pragma unroll
        for (int nt = 0; nt < 4; nt++)
#pragma unroll
            for (int q = 0; q < 4; q++) acc[mt][nt][q] = 0.f;

    const uint32_t smbase = smem_u32(&sm[0][0][0][0]);
    const uint32_t aoff = (uint32_t)((mb + (lane & 7) + (lane & 8)) * 48 + ((lane & 16) ? 16 : 0));
    const int bl = lane & 15;
    const uint32_t boff = (uint32_t)((nb + (bl & 7)) * 48 + ((bl & 8) ? 16 : 0));

    uint4 qa0 = make_uint4(0, 0, 0, 0), qa1 = qa0, qb0, qb1;
    if (okA) {
        qa0 = *reinterpret_cast<const uint4*>(Ap);
        qa1 = *reinterpret_cast<const uint4*>(Ap + 8);
    }
    qb0 = *reinterpret_cast<const uint4*>(Bp);
    qb1 = *reinterpret_cast<const uint4*>(Bp + 8);

    const int nk = K >> 4;
    for (int t = 0; t < nk; t++) {
        const int cur = t & 1;
        {
            __half* da = &sm[0][cur][split][rsel * RSTRIDE];
            *reinterpret_cast<uint4*>(da)     = qa0;
            *reinterpret_cast<uint4*>(da + 8) = qa1;
            __half* db = &sm[1][cur][split][rsel * RSTRIDE];
            *reinterpret_cast<uint4*>(db)     = qb0;
            *reinterpret_cast<uint4*>(db + 8) = qb1;
        }
        __syncthreads();

        if (t + 1 < nk) {
            const int k0 = (t + 1) * 16;
            if (okA) {
                qa0 = *reinterpret_cast<const uint4*>(Ap + k0);
                qa1 = *reinterpret_cast<const uint4*>(Ap + k0 + 8);
            }
            qb0 = *reinterpret_cast<const uint4*>(Bp + k0);
            qb1 = *reinterpret_cast<const uint4*>(Bp + k0 + 8);
        }

        const uint32_t Ah = smbase + (cur * 2 + 0) * REGB + aoff;
        const uint32_t Al = smbase + (cur * 2 + 1) * REGB + aoff;
        const uint32_t Bh = smbase + 4 * REGB + (cur * 2 + 0) * REGB + boff;
        const uint32_t Bl = smbase + 4 * REGB + (cur * 2 + 1) * REGB + boff;

        uint32_t bh[4][2], blo[4][2];
#pragma unroll
        for (int nt = 0; nt < 4; nt++) {
            LDSM_X2(bh[nt][0],  bh[nt][1],  Bh + nt * 384);
            LDSM_X2(blo[nt][0], blo[nt][1], Bl + nt * 384);
        }
#pragma unroll
        for (int mt = 0; mt < 4; mt++) {
            uint32_t ah[4], al[4];
            LDSM_X4(ah, Ah + mt * 768);
            LDSM_X4(al, Al + mt * 768);
#pragma unroll
            for (int nt = 0; nt < 4; nt++) {
                mma_f16(acc[mt][nt], ah, bh[nt]);    // hi*hi
                mma_f16(acc[mt][nt], al, bh[nt]);    // lo*hi
                mma_f16(acc[mt][nt], ah, blo[nt]);   // hi*lo
            }
        }
        __syncthreads();
    }

    // ---- epilogue: fp16 store + fused attention dots ----
    float* sred = reinterpret_cast<float*>(&sm[0][0][0][0]);  // overlay, [2][128][4]

    float asv0[4], asv1[4], adv0[4], adv1[4];
#pragma unroll
    for (int nt = 0; nt < 4; nt++) {
        int c = nb + nt * 8 + 2 * tg;
        asv0[nt] = a_src[head * 128 + c];
        asv1[nt] = a_src[head * 128 + c + 1];
        adv0[nt] = a_dst[head * 128 + c];
        adv1[nt] = a_dst[head * 128 + c + 1];
    }

#pragma unroll
    for (int mt = 0; mt < 4; mt++) {
#pragma unroll
        for (int rh = 0; rh < 2; rh++) {
            int rloc = mb + mt * 16 + rh * 8 + g;
            int r    = brow + rloc;
            float ps = 0.f, pd = 0.f;
#pragma unroll
            for (int nt = 0; nt < 4; nt++) {
                float c0 = acc[mt][nt][rh * 2];
                float c1 = acc[mt][nt][rh * 2 + 1];
                ps = fmaf(c0, asv0[nt], fmaf(c1, asv1[nt], ps));
                pd = fmaf(c0, adv0[nt], fmaf(c1, adv1[nt], pd));
                if (r < M) {
                    int col = head * 128 + nb + nt * 8 + 2 * tg;
                    *reinterpret_cast<__half2*>(hf + (size_t)r * FF + col) =
                        __floats2half2_rn(c0, c1);
                }
            }
            ps += __shfl_xor_sync(0xffffffffu, ps, 1);
            ps += __shfl_xor_sync(0xffffffffu, ps, 2);
            pd += __shfl_xor_sync(0xffffffffu, pd, 1);
            pd += __shfl_xor_sync(0xffffffffu, pd, 2);
            if (tg == 0) {
                sred[(0 * 128 + rloc) * 4 + wn] = ps;
                sred[(1 * 128 + rloc) * 4 + wn] = pd;
            }
        }
    }
    __syncthreads();
    if (tid < 128) {
        int r = brow + tid;
        if (r < M) {
            float s = sred[tid * 4] + sred[tid * 4 + 1] + sred[tid * 4 + 2] + sred[tid * 4 + 3];
            float d = sred[(128 + tid) * 4] + sred[(128 + tid) * 4 + 1]
                    + sred[(128 + tid) * 4 + 2] + sred[(128 + tid) * 4 + 3];
            as[r * HH + head] = s;
            ad[r * HH + head] = d;
        }
    }
}

__device__ __forceinline__ float lrelu(float z) { return z > 0.f ? z : SLOPE * z; }
__device__ __forceinline__ float sel4(float4 a, int h) {
    float v = a.x;
    if (h == 1) v = a.y;
    if (h == 2) v = a.z;
    if (h == 3) v = a.w;
    return v;
}

// ---------------- per-dst aggregation with segment softmax ----------------
// one warp per dst node. Pass 1: max. Pass 2: exp + denom, STORES unnormalized
// per-edge weights to g_wgt (kills the 32-lane-redundant exp in pass 3 — MUFU
// was the hidden serial resource). Pass 3: gather with broadcast weight load.
template <bool MEAN>
__global__ __launch_bounds__(256)
void k_agg(const __half* __restrict__ hfeat, const float* __restrict__ as,
           const float* __restrict__ ad, const float* __restrict__ bias,
           float* __restrict__ out, __half* __restrict__ ohi, __half* __restrict__ olo,
           int n)
{
    int w = (blockIdx.x * blockDim.x + threadIdx.x) >> 5;
    if (w >= n) return;
    int lane = threadIdx.x & 31;
    int start = g_rowptr[w], end = g_rowptr[w + 1];

    float4 adv = *reinterpret_cast<const float4*>(ad + (size_t)w * 4);

    // pass 1: per-head max
    float m0 = -3.4e38f, m1 = -3.4e38f, m2 = -3.4e38f, m3 = -3.4e38f;
    for (int j = start + lane; j < end; j += 32) {
        int s = g_srcsorted[j];
        float4 a = *reinterpret_cast<const float4*>(as + (size_t)s * 4);
        m0 = fmaxf(m0, lrelu(a.x + adv.x));
        m1 = fmaxf(m1, lrelu(a.y + adv.y));
        m2 = fmaxf(m2, lrelu(a.z + adv.z));
        m3 = fmaxf(m3, lrelu(a.w + adv.w));
    }
#pragma unroll
    for (int off = 16; off; off >>= 1) {
        m0 = fmaxf(m0, __shfl_xor_sync(0xffffffffu, m0, off));
        m1 = fmaxf(m1, __shfl_xor_sync(0xffffffffu, m1, off));
        m2 = fmaxf(m2, __shfl_xor_sync(0xffffffffu, m2, off));
        m3 = fmaxf(m3, __shfl_xor_sync(0xffffffffu, m3, off));
    }

    // pass 2: per-head sum of exp; store unnormalized weights per edge
    float d0 = 0.f, d1 = 0.f, d2 = 0.f, d3 = 0.f;
    for (int j = start + lane; j < end; j += 32) {
        int s = g_srcsorted[j];
        float4 a = *reinterpret_cast<const float4*>(as + (size_t)s * 4);
        float e0 = __expf(lrelu(a.x + adv.x) - m0);
        float e1 = __expf(lrelu(a.y + adv.y) - m1);
        float e2 = __expf(lrelu(a.z + adv.z) - m2);
        float e3 = __expf(lrelu(a.w + adv.w) - m3);
        d0 += e0; d1 += e1; d2 += e2; d3 += e3;
        *reinterpret_cast<float4*>(&g_wgt[(size_t)j * 4]) = make_float4(e0, e1, e2, e3);
    }
#pragma unroll
    for (int off = 16; off; off >>= 1) {
        d0 += __shfl_xor_sync(0xffffffffu, d0, off);
        d1 += __shfl_xor_sync(0xffffffffu, d1, off);
        d2 += __shfl_xor_sync(0xffffffffu, d2, off);
        d3 += __shfl_xor_sync(0xffffffffu, d3, off);
    }
    float i0 = 1.f / (d0 + 1e-16f);
    float i1 = 1.f / (d1 + 1e-16f);
    float i2 = 1.f / (d2 + 1e-16f);
    float i3 = 1.f / (d3 + 1e-16f);

    // pass 3: weighted fp16 feature gather; lane owns 16 contiguous channels
    const int hsel = lane >> 3;
    const float ii = sel4(make_float4(i0, i1, i2, i3), hsel);

    float4 acc[4];
#pragma unroll
    for (int k = 0; k < 4; k++) acc[k] = make_float4(0.f, 0.f, 0.f, 0.f);

    for (int j = start; j < end; j++) {
        int s = g_srcsorted[j];
        float4 wq = *reinterpret_cast<const float4*>(&g_wgt[(size_t)j * 4]);
        float wgt = sel4(wq, hsel) * ii;
        const uint4* hp = reinterpret_cast<const uint4*>(hfeat + (size_t)s * FF) + lane * 2;
        uint4 q0 = hp[0];
        uint4 q1 = hp[1];
        const __half2* ph = reinterpret_cast<const __half2*>(&q0);
#pragma unroll
        for (int k = 0; k < 2; k++) {
            float2 fa = __half22float2(ph[2 * k]);
            float2 fb = __half22float2(ph[2 * k + 1]);
            acc[k].x = fmaf(wgt, fa.x, acc[k].x);
            acc[k].y = fmaf(wgt, fa.y, acc[k].y);
            acc[k].z = fmaf(wgt, fb.x, acc[k].z);
            acc[k].w = fmaf(wgt, fb.y, acc[k].w);
        }
        const __half2* qh = reinterpret_cast<const __half2*>(&q1);
#pragma unroll
        for (int k = 0; k < 2; k++) {
            float2 fa = __half22float2(qh[2 * k]);
            float2 fb = __half22float2(qh[2 * k + 1]);
            acc[k + 2].x = fmaf(wgt, fa.x, acc[k + 2].x);
            acc[k + 2].y = fmaf(wgt, fa.y, acc[k + 2].y);
            acc[k + 2].z = fmaf(wgt, fb.x, acc[k + 2].z);
            acc[k + 2].w = fmaf(wgt, fb.y, acc[k + 2].w);
        }
    }

    if (!MEAN) {
        // bias + relu + fp16-split write (this IS layer-2's A operand)
        __half2* oh = reinterpret_cast<__half2*>(ohi + (size_t)w * FF + lane * 16);
        __half2* ol = reinterpret_cast<__half2*>(olo + (size_t)w * FF + lane * 16);
        const float4* bp = reinterpret_cast<const float4*>(bias);
#pragma unroll
        for (int k = 0; k < 4; k++) {
            float4 b4 = bp[lane * 4 + k];
            float4 v = acc[k];
            v.x = fmaxf(v.x + b4.x, 0.f);
            v.y = fmaxf(v.y + b4.y, 0.f);
            v.z = fmaxf(v.z + b4.z, 0.f);
            v.w = fmaxf(v.w + b4.w, 0.f);
            __half hx, lx, hy, ly, hz, lz, hw, lw;
            f16split(v.x, hx, lx); f16split(v.y, hy, ly);
            f16split(v.z, hz, lz); f16split(v.w, hw, lw);
            oh[2 * k]     = __halves2half2(hx, hy);
            oh[2 * k + 1] = __halves2half2(hz, hw);
            ol[2 * k]     = __halves2half2(lx, ly);
            ol[2 * k + 1] = __halves2half2(lz, lw);
        }
    } else {
        // mean over heads: sum lanes {l, l^8, l^16, l^24}, lanes 0..7 write 128 channels
#pragma unroll
        for (int k = 0; k < 4; k++) {
            acc[k].x += __shfl_xor_sync(0xffffffffu, acc[k].x, 8);
            acc[k].y += __shfl_xor_sync(0xffffffffu, acc[k].y, 8);
            acc[k].z += __shfl_xor_sync(0xffffffffu, acc[k].z, 8);
            acc[k].w += __shfl_xor_sync(0xffffffffu, acc[k].w, 8);
            acc[k].x += __shfl_xor_sync(0xffffffffu, acc[k].x, 16);
            acc[k].y += __shfl_xor_sync(0xffffffffu, acc[k].y, 16);
            acc[k].z += __shfl_xor_sync(0xffffffffu, acc[k].z, 16);
            acc[k].w += __shfl_xor_sync(0xffffffffu, acc[k].w, 16);
        }
        if (lane < 8) {
            float4* op = reinterpret_cast<float4*>(out + (size_t)w * COUT);
            const float4* bp = reinterpret_cast<const float4*>(bias);
#pragma unroll
            for (int k = 0; k < 4; k++) {
                float4 b4 = bp[lane * 4 + k];
                float4 v = acc[k];
                v.x = 0.25f * v.x + b4.x; v.y = 0.25f * v.y + b4.y;
                v.z = 0.25f * v.z + b4.z; v.w = 0.25f * v.w + b4.w;
                op[lane * 4 + k] = v;
            }
        }
    }
}

// ---------------- host ----------------
extern "C" void kernel_launch(void* const* d_in, const int* in_sizes, int n_in,
                              void* d_out, int out_size)
{
    const float* x      = (const float*)d_in[0];
    const int*   ei     = (const int*)d_in[1];
    const float* W1     = (const float*)d_in[2];
    const float* a_src1 = (const float*)d_in[3];
    const float* a_dst1 = (const float*)d_in[4];
    const float* b1     = (const float*)d_in[5];
    const float* W2     = (const float*)d_in[6];
    const float* a_src2 = (const float*)d_in[7];
    const float* a_dst2 = (const float*)d_in[8];
    const float* b2     = (const float*)d_in[9];

    const int N = in_sizes[0] / CIN;
    const int E = in_sizes[1] / 2;

    void *p_hf1, *p_hf2, *p_xh, *p_xl, *p_ah, *p_al, *p_w1h, *p_w1l, *p_w2h, *p_w2l;
    void *p_as1, *p_ad1, *p_as2, *p_ad2, *p_cnt;
    cudaGetSymbolAddress(&p_hf1, g_hf1);
    cudaGetSymbolAddress(&p_hf2, g_hf2);
    cudaGetSymbolAddress(&p_xh, g_xs_hi);
    cudaGetSymbolAddress(&p_xl, g_xs_lo);
    cudaGetSymbolAddress(&p_ah, g_a2_hi);
    cudaGetSymbolAddress(&p_al, g_a2_lo);
    cudaGetSymbolAddress(&p_w1h, g_w1_hi);
    cudaGetSymbolAddress(&p_w1l, g_w1_lo);
    cudaGetSymbolAddress(&p_w2h, g_w2_hi);
    cudaGetSymbolAddress(&p_w2l, g_w2_lo);
    cudaGetSymbolAddress(&p_as1, g_as1);
    cudaGetSymbolAddress(&p_ad1, g_ad1);
    cudaGetSymbolAddress(&p_as2, g_as2);
    cudaGetSymbolAddress(&p_ad2, g_ad2);
    cudaGetSymbolAddress(&p_cnt, g_counts);
    __half* hf1 = (__half*)p_hf1;
    __half* hf2 = (__half*)p_hf2;
    float* as1 = (float*)p_as1;
    float* ad1 = (float*)p_ad1;
    float* as2 = (float*)p_as2;
    float* ad2 = (float*)p_ad2;
    float* out = (float*)d_out;

    // lazily-created side stream + events (created on the uncaptured
    // correctness call; only the launches/events below are captured)
    static cudaStream_t s2 = nullptr;
    static cudaEvent_t ev0 = nullptr, ev1 = nullptr;
    if (!s2) {
        cudaStreamCreateWithFlags(&s2, cudaStreamNonBlocking);
        cudaEventCreateWithFlags(&ev0, cudaEventDisableTiming);
        cudaEventCreateWithFlags(&ev1, cudaEventDisableTiming);
    }

    // fork: CSR build on s2, overlapping splits + GEMM1 on the main stream
    cudaEventRecord(ev0, 0);
    cudaStreamWaitEvent(s2, ev0, 0);
    cudaMemsetAsync(p_cnt, 0, (size_t)N * sizeof(int), s2);
    k_count<<<(E + 255) / 256, 256, 0, s2>>>(ei, E);
    k_scan<<<1, 1024, 0, s2>>>(N);
    k_scatter<<<(E + N + 255) / 256, 256, 0, s2>>>(ei, E, N);
    cudaEventRecord(ev1, s2);

    // pre-split operands (main stream)
    k_splitW<<<dim3(FF / 32, CIN / 32), dim3(32, 8)>>>(W1, (__half*)p_w1h, (__half*)p_w1l, CIN);
    k_splitW<<<dim3(FF / 32, FF / 32),  dim3(32, 8)>>>(W2, (__half*)p_w2h, (__half*)p_w2l, FF);
    const int tot8 = N * CIN / 8;
    k_splitX<<<(tot8 + 255) / 256, 256>>>(x, (__half*)p_xh, (__half*)p_xl, tot8);

    const int warpsGrid = (N * 32 + 255) / 256;
    const dim3 gg(HH, (N + 127) / 128);

    // layer 1
    k_gemm<<<gg, 256>>>((__half*)p_xh, (__half*)p_xl, (__half*)p_w1h, (__half*)p_w1l,
                        hf1, as1, ad1, a_src1, a_dst1, N, CIN);

    // join: CSR must be done before aggregation
    cudaStreamWaitEvent(0, ev1, 0);

    k_agg<false><<<warpsGrid, 256>>>(hf1, as1, ad1, b1, nullptr,
                                     (__half*)p_ah, (__half*)p_al, N);

    // layer 2 (A = relu'd split halves from k_agg)
    k_gemm<<<gg, 256>>>((__half*)p_ah, (__half*)p_al, (__half*)p_w2h, (__half*)p_w2l,
                        hf2, as2, ad2, a_src2, a_dst2, N, FF);
    k_agg<true><<<warpsGrid, 256>>>(hf2, as2, ad2, b2, out, nullptr, nullptr, N);
}

// round 17
// speedup vs baseline: 2.5621x; 1.2144x over previous
#include <cuda_runtime.h>
#include <cuda_fp16.h>
#include <cstdint>

// Problem constants (fixed by the dataset)
#define NN   10000
#define EE   320000
#define HH   4
#define CIN  256
#define FF   512          // H*HID = H*OUT = per-node feature width in both layers
#define COUT 128
#define SLOPE 0.2f

// ---------------- scratch (static device globals; no allocation) ----------------
__device__ __half g_hf1[NN * FF];       // layer-1 features (fp16, gather source)
__device__ __half g_hf2[NN * FF];       // layer-2 features
__device__ __half g_xs_hi[NN * CIN];    // x cast to fp16 (A operand, layer 1)
__device__ __half g_a2_hi[NN * FF];     // relu(layer1 out) fp16 (A operand, layer 2)
__device__ __half g_w1_hi[FF * CIN];    // W1^T [512][256] split hi/lo
__device__ __half g_w1_lo[FF * CIN];
__device__ __half g_w2_hi[FF * FF];     // W2^T [512][512] split hi/lo
__device__ __half g_w2_lo[FF * FF];
__device__ float g_as1[NN * HH];
__device__ float g_ad1[NN * HH];
__device__ float g_as2[NN * HH];
__device__ float g_ad2[NN * HH];
__device__ float g_wgt[(EE + NN) * HH]; // per-edge unnormalized softmax weights (4 heads)
__device__ int   g_counts[NN];
__device__ int   g_rowptr[NN + 1];
__device__ int   g_cursor[NN];
__device__ int   g_srcsorted[EE + NN];

// ---------------- CSR build ----------------
__global__ void k_count(const int* __restrict__ ei, int E) {
    int i = blockIdx.x * blockDim.x + threadIdx.x;
    if (i < E) atomicAdd(&g_counts[ei[E + i]], 1);
}

// single-block exclusive scan of (g_counts[i]+1) -> g_rowptr, g_cursor
__global__ void k_scan(int n) {
    __shared__ int sb[1024];
    int tid = threadIdx.x;
    int per = (n + 1023) >> 10;
    int base = tid * per;
    int sum = 0;
    for (int i = 0; i < per; i++) {
        int idx = base + i;
        if (idx < n) sum += g_counts[idx] + 1;
    }
    sb[tid] = sum;
    __syncthreads();
    for (int off = 1; off < 1024; off <<= 1) {
        int v = (tid >= off) ? sb[tid - off] : 0;
        __syncthreads();
        sb[tid] += v;
        __syncthreads();
    }
    int run = sb[tid] - sum;
    for (int i = 0; i < per; i++) {
        int idx = base + i;
        if (idx < n) {
            g_rowptr[idx] = run;
            g_cursor[idx] = run;
            run += g_counts[idx] + 1;
        }
    }
    if (tid == 1023) g_rowptr[n] = sb[1023];
}

__global__ void k_scatter(const int* __restrict__ ei, int E, int n) {
    int i = blockIdx.x * blockDim.x + threadIdx.x;
    int total = E + n;
    if (i >= total) return;
    int s, d;
    if (i < E) { s = ei[i]; d = ei[E + i]; }
    else       { s = i - E; d = s; }
    int pos = atomicAdd(&g_cursor[d], 1);
    g_srcsorted[pos] = s;
}

// ---------------- fp16 split helpers ----------------
__device__ __forceinline__ void f16split(float v, __half& hi, __half& lo) {
    hi = __float2half_rn(v);
    lo = __float2half_rn(v - __half2float(hi));
}

__device__ __forceinline__ void mma_f16(float* d, const uint32_t* a, const uint32_t* b) {
    asm volatile(
        "mma.sync.aligned.m16n8k16.row.col.f32.f16.f16.f32 "
        "{%0,%1,%2,%3}, {%4,%5,%6,%7}, {%8,%9}, {%0,%1,%2,%3};"
        : "+f"(d[0]), "+f"(d[1]), "+f"(d[2]), "+f"(d[3])
        : "r"(a[0]), "r"(a[1]), "r"(a[2]), "r"(a[3]), "r"(b[0]), "r"(b[1]));
}

__device__ __forceinline__ uint32_t smem_u32(const void* p) {
    uint32_t a;
    asm("{ .reg .u64 t; cvta.to.shared.u64 t, %1; cvt.u32.u64 %0, t; }" : "=r"(a) : "l"(p));
    return a;
}

#define LDSM_X4(r, addr) \
    asm volatile("ldmatrix.sync.aligned.m8n8.x4.shared.b16 {%0,%1,%2,%3}, [%4];" \
        : "=r"((r)[0]), "=r"((r)[1]), "=r"((r)[2]), "=r"((r)[3]) : "r"(addr))
#define LDSM_X2(r0, r1, addr) \
    asm volatile("ldmatrix.sync.aligned.m8n8.x2.shared.b16 {%0,%1}, [%2];" \
        : "=r"(r0), "=r"(r1) : "r"(addr))

// ---------------- pre-split / cast kernels ----------------
// W [K][512] -> hi/lo [512][K]  (transpose + split; W stays exactly represented)
__global__ void k_splitW(const float* __restrict__ W, __half* __restrict__ whi,
                         __half* __restrict__ wlo, int K)
{
    __shared__ float t[32][33];
    int n0 = blockIdx.x * 32, k0 = blockIdx.y * 32;
    int tx = threadIdx.x, ty = threadIdx.y;
#pragma unroll
    for (int i = 0; i < 32; i += 8)
        t[ty + i][tx] = W[(size_t)(k0 + ty + i) * FF + n0 + tx];
    __syncthreads();
#pragma unroll
    for (int i = 0; i < 32; i += 8) {
        float v = t[tx][ty + i];
        __half h, l;
        f16split(v, h, l);
        size_t o = (size_t)(n0 + ty + i) * K + k0 + tx;
        whi[o] = h;
        wlo[o] = l;
    }
}

// x [N][CIN] -> fp16 (A truncated; compensated on the W side only)
__global__ void k_castX(const float* __restrict__ x, __half* __restrict__ xhi, int total8)
{
    int i = blockIdx.x * blockDim.x + threadIdx.x;
    if (i >= total8) return;
    const float4* xp = reinterpret_cast<const float4*>(x) + (size_t)i * 2;
    float4 v0 = xp[0], v1 = xp[1];
    __half2 h0 = __floats2half2_rn(v0.x, v0.y);
    __half2 h1 = __floats2half2_rn(v0.z, v0.w);
    __half2 h2 = __floats2half2_rn(v1.x, v1.y);
    __half2 h3 = __floats2half2_rn(v1.z, v1.w);
    uint4 o;
    o.x = *reinterpret_cast<uint32_t*>(&h0);
    o.y = *reinterpret_cast<uint32_t*>(&h1);
    o.z = *reinterpret_cast<uint32_t*>(&h2);
    o.w = *reinterpret_cast<uint32_t*>(&h3);
    reinterpret_cast<uint4*>(xhi)[i] = o;
}

// ---------------- fused GEMM + attention-coefficient kernel ----------------
// C = A16 @ (Whi + Wlo): 2-term compensated mma (A truncated fp16, W exact split).
// CTA: 128 rows x one head. 8 warps 2x4; warp tile 64x32.
// SMEM regions per stage: [A, Bhi, Blo]; rows padded to 24 halves (48B).
#define RSTRIDE 24                 // halves per smem row
#define REGION  (128 * RSTRIDE)    // halves per region (3072)
#define REGB    (REGION * 2)       // bytes per region (6144)

__global__ __launch_bounds__(256, 2)
void k_gemm(const __half* __restrict__ Ahi,
            const __half* __restrict__ Bhi, const __half* __restrict__ Blo,
            __half* __restrict__ hf, float* __restrict__ as, float* __restrict__ ad,
            const float* __restrict__ a_src, const float* __restrict__ a_dst,
            int M, int K)
{
    __shared__ __align__(16) __half sm[2][3][REGION];  // [stage][A/Bhi/Blo]

    const int tid  = threadIdx.x;
    const int wid  = tid >> 5;
    const int lane = tid & 31;
    const int g    = lane >> 2;
    const int tg   = lane & 3;
    const int wm   = wid >> 2;
    const int wn   = wid & 3;
    const int mb   = wm * 64;
    const int nb   = wn * 32;

    const int head = blockIdx.x;
    const int brow = blockIdx.y * 128;

    // staging: tid<128 -> A row rsel; tid>=128 -> B row rsel (hi+lo)
    const int rsel  = tid & 127;
    const bool isA  = tid < 128;
    const int row   = brow + rsel;
    const bool okA  = row < M;
    const __half* Ap  = Ahi + (size_t)row * K;
    const __half* BpH = Bhi + (size_t)(head * 128 + rsel) * K;
    const __half* BpL = Blo + (size_t)(head * 128 + rsel) * K;

    float acc[4][4][4];
#pragma unroll
    for (int mt = 0; mt < 4; mt++)
#pragma unroll
        for (int nt = 0; nt < 4; nt++)
#pragma unroll
            for (int q = 0; q < 4; q++) acc[mt][nt][q] = 0.f;

    const uint32_t smbase = smem_u32(&sm[0][0][0]);
    const uint32_t aoff = (uint32_t)((mb + (lane & 7) + (lane & 8)) * 48 + ((lane & 16) ? 16 : 0));
    const int bl = lane & 15;
    const uint32_t boff = (uint32_t)((nb + (bl & 7)) * 48 + ((bl & 8) ? 16 : 0));

    // preload first chunk
    uint4 q0 = make_uint4(0, 0, 0, 0), q1 = q0, q2 = q0, q3 = q0;
    if (isA) {
        if (okA) {
            q0 = *reinterpret_cast<const uint4*>(Ap);
            q1 = *reinterpret_cast<const uint4*>(Ap + 8);
        }
    } else {
        q0 = *reinterpret_cast<const uint4*>(BpH);
        q1 = *reinterpret_cast<const uint4*>(BpH + 8);
        q2 = *reinterpret_cast<const uint4*>(BpL);
        q3 = *reinterpret_cast<const uint4*>(BpL + 8);
    }

    const int nk = K >> 4;
    for (int t = 0; t < nk; t++) {
        const int cur = t & 1;
        {
            __half* d0 = isA ? &sm[cur][0][rsel * RSTRIDE] : &sm[cur][1][rsel * RSTRIDE];
            *reinterpret_cast<uint4*>(d0)     = q0;
            *reinterpret_cast<uint4*>(d0 + 8) = q1;
            if (!isA) {
                __half* d2 = &sm[cur][2][rsel * RSTRIDE];
                *reinterpret_cast<uint4*>(d2)     = q2;
                *reinterpret_cast<uint4*>(d2 + 8) = q3;
            }
        }
        __syncthreads();

        if (t + 1 < nk) {
            const int k0 = (t + 1) * 16;
            if (isA) {
                if (okA) {
                    q0 = *reinterpret_cast<const uint4*>(Ap + k0);
                    q1 = *reinterpret_cast<const uint4*>(Ap + k0 + 8);
                }
            } else {
                q0 = *reinterpret_cast<const uint4*>(BpH + k0);
                q1 = *reinterpret_cast<const uint4*>(BpH + k0 + 8);
                q2 = *reinterpret_cast<const uint4*>(BpL + k0);
                q3 = *reinterpret_cast<const uint4*>(BpL + k0 + 8);
            }
        }

        const uint32_t Ah = smbase + (cur * 3 + 0) * REGB + aoff;
        const uint32_t Bh = smbase + (cur * 3 + 1) * REGB + boff;
        const uint32_t Bl = smbase + (cur * 3 + 2) * REGB + boff;

        uint32_t bh[4][2], blx[4][2];
#pragma unroll
        for (int nt = 0; nt < 4; nt++) {
            LDSM_X2(bh[nt][0],  bh[nt][1],  Bh + nt * 384);
            LDSM_X2(blx[nt][0], blx[nt][1], Bl + nt * 384);
        }
#pragma unroll
        for (int mt = 0; mt < 4; mt++) {
            uint32_t ah[4];
            LDSM_X4(ah, Ah + mt * 768);
#pragma unroll
            for (int nt = 0; nt < 4; nt++) {
                mma_f16(acc[mt][nt], ah, bh[nt]);    // A * W_hi
                mma_f16(acc[mt][nt], ah, blx[nt]);   // A * W_lo
            }
        }
        __syncthreads();
    }

    // ---- epilogue: fp16 store + fused attention dots ----
    float* sred = reinterpret_cast<float*>(&sm[0][0][0]);  // overlay, [2][128][4]

    float asv0[4], asv1[4], adv0[4], adv1[4];
#pragma unroll
    for (int nt = 0; nt < 4; nt++) {
        int c = nb + nt * 8 + 2 * tg;
        asv0[nt] = a_src[head * 128 + c];
        asv1[nt] = a_src[head * 128 + c + 1];
        adv0[nt] = a_dst[head * 128 + c];
        adv1[nt] = a_dst[head * 128 + c + 1];
    }

#pragma unroll
    for (int mt = 0; mt < 4; mt++) {
#pragma unroll
        for (int rh = 0; rh < 2; rh++) {
            int rloc = mb + mt * 16 + rh * 8 + g;
            int r    = brow + rloc;
            float ps = 0.f, pd = 0.f;
#pragma unroll
            for (int nt = 0; nt < 4; nt++) {
                float c0 = acc[mt][nt][rh * 2];
                float c1 = acc[mt][nt][rh * 2 + 1];
                ps = fmaf(c0, asv0[nt], fmaf(c1, asv1[nt], ps));
                pd = fmaf(c0, adv0[nt], fmaf(c1, adv1[nt], pd));
                if (r < M) {
                    int col = head * 128 + nb + nt * 8 + 2 * tg;
                    *reinterpret_cast<__half2*>(hf + (size_t)r * FF + col) =
                        __floats2half2_rn(c0, c1);
                }
            }
            ps += __shfl_xor_sync(0xffffffffu, ps, 1);
            ps += __shfl_xor_sync(0xffffffffu, ps, 2);
            pd += __shfl_xor_sync(0xffffffffu, pd, 1);
            pd += __shfl_xor_sync(0xffffffffu, pd, 2);
            if (tg == 0) {
                sred[(0 * 128 + rloc) * 4 + wn] = ps;
                sred[(1 * 128 + rloc) * 4 + wn] = pd;
            }
        }
    }
    __syncthreads();
    if (tid < 128) {
        int r = brow + tid;
        if (r < M) {
            float s = sred[tid * 4] + sred[tid * 4 + 1] + sred[tid * 4 + 2] + sred[tid * 4 + 3];
            float d = sred[(128 + tid) * 4] + sred[(128 + tid) * 4 + 1]
                    + sred[(128 + tid) * 4 + 2] + sred[(128 + tid) * 4 + 3];
            as[r * HH + head] = s;
            ad[r * HH + head] = d;
        }
    }
}

__device__ __forceinline__ float lrelu(float z) { return z > 0.f ? z : SLOPE * z; }
__device__ __forceinline__ float sel4(float4 a, int h) {
    float v = a.x;
    if (h == 1) v = a.y;
    if (h == 2) v = a.z;
    if (h == 3) v = a.w;
    return v;
}

__device__ __forceinline__ void acc_feat(float4* acc, const uint4& q0, const uint4& q1,
                                         float wgt) {
    const __half2* ph = reinterpret_cast<const __half2*>(&q0);
#pragma unroll
    for (int k = 0; k < 2; k++) {
        float2 fa = __half22float2(ph[2 * k]);
        float2 fb = __half22float2(ph[2 * k + 1]);
        acc[k].x = fmaf(wgt, fa.x, acc[k].x);
        acc[k].y = fmaf(wgt, fa.y, acc[k].y);
        acc[k].z = fmaf(wgt, fb.x, acc[k].z);
        acc[k].w = fmaf(wgt, fb.y, acc[k].w);
    }
    const __half2* qh = reinterpret_cast<const __half2*>(&q1);
#pragma unroll
    for (int k = 0; k < 2; k++) {
        float2 fa = __half22float2(qh[2 * k]);
        float2 fb = __half22float2(qh[2 * k + 1]);
        acc[k + 2].x = fmaf(wgt, fa.x, acc[k + 2].x);
        acc[k + 2].y = fmaf(wgt, fa.y, acc[k + 2].y);
        acc[k + 2].z = fmaf(wgt, fb.x, acc[k + 2].z);
        acc[k + 2].w = fmaf(wgt, fb.y, acc[k + 2].w);
    }
}

// ---------------- per-dst aggregation with segment softmax ----------------
// one warp per dst node. Pass 1: max. Pass 2: exp + denom, stores unnormalized
// weights. Pass 3: batch-4 gather (8 uint4 loads in flight before any FMA).
template <bool MEAN>
__global__ __launch_bounds__(256)
void k_agg(const __half* __restrict__ hfeat, const float* __restrict__ as,
           const float* __restrict__ ad, const float* __restrict__ bias,
           float* __restrict__ out, __half* __restrict__ ohi, int n)
{
    int w = (blockIdx.x * blockDim.x + threadIdx.x) >> 5;
    if (w >= n) return;
    int lane = threadIdx.x & 31;
    int start = g_rowptr[w], end = g_rowptr[w + 1];

    float4 adv = *reinterpret_cast<const float4*>(ad + (size_t)w * 4);

    // pass 1: per-head max
    float m0 = -3.4e38f, m1 = -3.4e38f, m2 = -3.4e38f, m3 = -3.4e38f;
    for (int j = start + lane; j < end; j += 32) {
        int s = g_srcsorted[j];
        float4 a = *reinterpret_cast<const float4*>(as + (size_t)s * 4);
        m0 = fmaxf(m0, lrelu(a.x + adv.x));
        m1 = fmaxf(m1, lrelu(a.y + adv.y));
        m2 = fmaxf(m2, lrelu(a.z + adv.z));
        m3 = fmaxf(m3, lrelu(a.w + adv.w));
    }
#pragma unroll
    for (int off = 16; off; off >>= 1) {
        m0 = fmaxf(m0, __shfl_xor_sync(0xffffffffu, m0, off));
        m1 = fmaxf(m1, __shfl_xor_sync(0xffffffffu, m1, off));
        m2 = fmaxf(m2, __shfl_xor_sync(0xffffffffu, m2, off));
        m3 = fmaxf(m3, __shfl_xor_sync(0xffffffffu, m3, off));
    }

    // pass 2: per-head sum of exp; store unnormalized weights per edge
    float d0 = 0.f, d1 = 0.f, d2 = 0.f, d3 = 0.f;
    for (int j = start + lane; j < end; j += 32) {
        int s = g_srcsorted[j];
        float4 a = *reinterpret_cast<const float4*>(as + (size_t)s * 4);
        float e0 = __expf(lrelu(a.x + adv.x) - m0);
        float e1 = __expf(lrelu(a.y + adv.y) - m1);
        float e2 = __expf(lrelu(a.z + adv.z) - m2);
        float e3 = __expf(lrelu(a.w + adv.w) - m3);
        d0 += e0; d1 += e1; d2 += e2; d3 += e3;
        *reinterpret_cast<float4*>(&g_wgt[(size_t)j * 4]) = make_float4(e0, e1, e2, e3);
    }
#pragma unroll
    for (int off = 16; off; off >>= 1) {
        d0 += __shfl_xor_sync(0xffffffffu, d0, off);
        d1 += __shfl_xor_sync(0xffffffffu, d1, off);
        d2 += __shfl_xor_sync(0xffffffffu, d2, off);
        d3 += __shfl_xor_sync(0xffffffffu, d3, off);
    }
    float i0 = 1.f / (d0 + 1e-16f);
    float i1 = 1.f / (d1 + 1e-16f);
    float i2 = 1.f / (d2 + 1e-16f);
    float i3 = 1.f / (d3 + 1e-16f);

    // pass 3: weighted fp16 feature gather; lane owns 16 contiguous channels
    const int hsel = lane >> 3;
    const float ii = sel4(make_float4(i0, i1, i2, i3), hsel);

    float4 acc[4];
#pragma unroll
    for (int k = 0; k < 4; k++) acc[k] = make_float4(0.f, 0.f, 0.f, 0.f);

    int j = start;
    for (; j + 4 <= end; j += 4) {
        int s0 = g_srcsorted[j + 0];
        int s1 = g_srcsorted[j + 1];
        int s2 = g_srcsorted[j + 2];
        int s3 = g_srcsorted[j + 3];
        float4 w0 = *reinterpret_cast<const float4*>(&g_wgt[(size_t)(j + 0) * 4]);
        float4 w1 = *reinterpret_cast<const float4*>(&g_wgt[(size_t)(j + 1) * 4]);
        float4 w2 = *reinterpret_cast<const float4*>(&g_wgt[(size_t)(j + 2) * 4]);
        float4 w3 = *reinterpret_cast<const float4*>(&g_wgt[(size_t)(j + 3) * 4]);
        const uint4* h0 = reinterpret_cast<const uint4*>(hfeat + (size_t)s0 * FF) + lane * 2;
        const uint4* h1 = reinterpret_cast<const uint4*>(hfeat + (size_t)s1 * FF) + lane * 2;
        const uint4* h2 = reinterpret_cast<const uint4*>(hfeat + (size_t)s2 * FF) + lane * 2;
        const uint4* h3 = reinterpret_cast<const uint4*>(hfeat + (size_t)s3 * FF) + lane * 2;
        uint4 a0 = h0[0], b0 = h0[1];
        uint4 a1 = h1[0], b1 = h1[1];
        uint4 a2 = h2[0], b2 = h2[1];
        uint4 a3 = h3[0], b3 = h3[1];
        acc_feat(acc, a0, b0, sel4(w0, hsel) * ii);
        acc_feat(acc, a1, b1, sel4(w1, hsel) * ii);
        acc_feat(acc, a2, b2, sel4(w2, hsel) * ii);
        acc_feat(acc, a3, b3, sel4(w3, hsel) * ii);
    }
    for (; j < end; j++) {
        int s = g_srcsorted[j];
        float4 wq = *reinterpret_cast<const float4*>(&g_wgt[(size_t)j * 4]);
        const uint4* hp = reinterpret_cast<const uint4*>(hfeat + (size_t)s * FF) + lane * 2;
        uint4 q0 = hp[0], q1 = hp[1];
        acc_feat(acc, q0, q1, sel4(wq, hsel) * ii);
    }

    if (!MEAN) {
        // bias + relu + fp16 write (this IS layer-2's A operand, truncated)
        __half2* oh = reinterpret_cast<__half2*>(ohi + (size_t)w * FF + lane * 16);
        const float4* bp = reinterpret_cast<const float4*>(bias);
#pragma unroll
        for (int k = 0; k < 4; k++) {
            float4 b4 = bp[lane * 4 + k];
            float4 v = acc[k];
            v.x = fmaxf(v.x + b4.x, 0.f);
            v.y = fmaxf(v.y + b4.y, 0.f);
            v.z = fmaxf(v.z + b4.z, 0.f);
            v.w = fmaxf(v.w + b4.w, 0.f);
            oh[2 * k]     = __floats2half2_rn(v.x, v.y);
            oh[2 * k + 1] = __floats2half2_rn(v.z, v.w);
        }
    } else {
        // mean over heads: sum lanes {l, l^8, l^16, l^24}, lanes 0..7 write 128 channels
#pragma unroll
        for (int k = 0; k < 4; k++) {
            acc[k].x += __shfl_xor_sync(0xffffffffu, acc[k].x, 8);
            acc[k].y += __shfl_xor_sync(0xffffffffu, acc[k].y, 8);
            acc[k].z += __shfl_xor_sync(0xffffffffu, acc[k].z, 8);
            acc[k].w += __shfl_xor_sync(0xffffffffu, acc[k].w, 8);
            acc[k].x += __shfl_xor_sync(0xffffffffu, acc[k].x, 16);
            acc[k].y += __shfl_xor_sync(0xffffffffu, acc[k].y, 16);
            acc[k].z += __shfl_xor_sync(0xffffffffu, acc[k].z, 16);
            acc[k].w += __shfl_xor_sync(0xffffffffu, acc[k].w, 16);
        }
        if (lane < 8) {
            float4* op = reinterpret_cast<float4*>(out + (size_t)w * COUT);
            const float4* bp = reinterpret_cast<const float4*>(bias);
#pragma unroll
            for (int k = 0; k < 4; k++) {
                float4 b4 = bp[lane * 4 + k];
                float4 v = acc[k];
                v.x = 0.25f * v.x + b4.x; v.y = 0.25f * v.y + b4.y;
                v.z = 0.25f * v.z + b4.z; v.w = 0.25f * v.w + b4.w;
                op[lane * 4 + k] = v;
            }
        }
    }
}

// ---------------- host ----------------
extern "C" void kernel_launch(void* const* d_in, const int* in_sizes, int n_in,
                              void* d_out, int out_size)
{
    const float* x      = (const float*)d_in[0];
    const int*   ei     = (const int*)d_in[1];
    const float* W1     = (const float*)d_in[2];
    const float* a_src1 = (const float*)d_in[3];
    const float* a_dst1 = (const float*)d_in[4];
    const float* b1     = (const float*)d_in[5];
    const float* W2     = (const float*)d_in[6];
    const float* a_src2 = (const float*)d_in[7];
    const float* a_dst2 = (const float*)d_in[8];
    const float* b2     = (const float*)d_in[9];

    const int N = in_sizes[0] / CIN;
    const int E = in_sizes[1] / 2;

    void *p_hf1, *p_hf2, *p_xh, *p_ah, *p_w1h, *p_w1l, *p_w2h, *p_w2l;
    void *p_as1, *p_ad1, *p_as2, *p_ad2, *p_cnt;
    cudaGetSymbolAddress(&p_hf1, g_hf1);
    cudaGetSymbolAddress(&p_hf2, g_hf2);
    cudaGetSymbolAddress(&p_xh, g_xs_hi);
    cudaGetSymbolAddress(&p_ah, g_a2_hi);
    cudaGetSymbolAddress(&p_w1h, g_w1_hi);
    cudaGetSymbolAddress(&p_w1l, g_w1_lo);
    cudaGetSymbolAddress(&p_w2h, g_w2_hi);
    cudaGetSymbolAddress(&p_w2l, g_w2_lo);
    cudaGetSymbolAddress(&p_as1, g_as1);
    cudaGetSymbolAddress(&p_ad1, g_ad1);
    cudaGetSymbolAddress(&p_as2, g_as2);
    cudaGetSymbolAddress(&p_ad2, g_ad2);
    cudaGetSymbolAddress(&p_cnt, g_counts);
    __half* hf1 = (__half*)p_hf1;
    __half* hf2 = (__half*)p_hf2;
    float* as1 = (float*)p_as1;
    float* ad1 = (float*)p_ad1;
    float* as2 = (float*)p_as2;
    float* ad2 = (float*)p_ad2;
    float* out = (float*)d_out;

    // lazily-created side stream + events (created on the uncaptured
    // correctness call; only the launches/events below are captured)
    static cudaStream_t s2 = nullptr;
    static cudaEvent_t ev0 = nullptr, ev1 = nullptr, ev2 = nullptr;
    if (!s2) {
        cudaStreamCreateWithFlags(&s2, cudaStreamNonBlocking);
        cudaEventCreateWithFlags(&ev0, cudaEventDisableTiming);
        cudaEventCreateWithFlags(&ev1, cudaEventDisableTiming);
        cudaEventCreateWithFlags(&ev2, cudaEventDisableTiming);
    }

    // fork: CSR build + W2 split on s2, overlapping main-stream layer 1
    cudaEventRecord(ev0, 0);
    cudaStreamWaitEvent(s2, ev0, 0);
    cudaMemsetAsync(p_cnt, 0, (size_t)N * sizeof(int), s2);
    k_count<<<(E + 255) / 256, 256, 0, s2>>>(ei, E);
    k_scan<<<1, 1024, 0, s2>>>(N);
    k_scatter<<<(E + N + 255) / 256, 256, 0, s2>>>(ei, E, N);
    cudaEventRecord(ev1, s2);                      // CSR ready (gates agg1)
    k_splitW<<<dim3(FF / 32, FF / 32), dim3(32, 8), 0, s2>>>(W2, (__half*)p_w2h, (__half*)p_w2l, FF);
    cudaEventRecord(ev2, s2);                      // W2 ready (gates gemm2)

    // main stream: layer-1 operand prep + GEMM
    k_splitW<<<dim3(FF / 32, CIN / 32), dim3(32, 8)>>>(W1, (__half*)p_w1h, (__half*)p_w1l, CIN);
    const int tot8 = N * CIN / 8;
    k_castX<<<(tot8 + 255) / 256, 256>>>(x, (__half*)p_xh, tot8);

    const int warpsGrid = (N * 32 + 255) / 256;
    const dim3 gg(HH, (N + 127) / 128);

    // layer 1
    k_gemm<<<gg, 256>>>((__half*)p_xh, (__half*)p_w1h, (__half*)p_w1l,
                        hf1, as1, ad1, a_src1, a_dst1, N, CIN);

    cudaStreamWaitEvent(0, ev1, 0);   // CSR join
    k_agg<false><<<warpsGrid, 256>>>(hf1, as1, ad1, b1, nullptr, (__half*)p_ah, N);

    cudaStreamWaitEvent(0, ev2, 0);   // W2 join
    // layer 2 (A = relu'd fp16 from k_agg)
    k_gemm<<<gg, 256>>>((__half*)p_ah, (__half*)p_w2h, (__half*)p_w2l,
                        hf2, as2, ad2, a_src2, a_dst2, N, FF);
    k_agg<true><<<warpsGrid, 256>>>(hf2, as2, ad2, b2, out, nullptr, N);
}